// round 3
// baseline (speedup 1.0000x reference)
#include <cuda_runtime.h>

// Problem constants
#define B_  8
#define C_  512          // channels == D
#define N_  16384        // H*W
#define K_  150          // num classes

// ---------------------------------------------------------------------------
// Device scratch (no allocations allowed; static __device__ arrays)
// ---------------------------------------------------------------------------
__device__ float g_attn    [B_ * K_ * N_];   // coupled_attn, later reused as masks buffer
__device__ float g_cls_attn[B_ * K_ * N_];   // softmax over n
__device__ float g_pos_attn[B_ * K_ * N_];   // softmax over k
__device__ float g_P       [B_ * K_ * C_];   // cls_attn @ img_feat
__device__ float g_acls    [B_ * K_ * C_];   // aligned_cls
__device__ float g_M2      [K_ * C_];        // cls @ W_feat^T
__device__ float g_ST      [B_ * K_ * K_];   // ST[k'][k] = sum_d acls[k'][d]*M2[k][d]

// ---------------------------------------------------------------------------
// NN GEMM:  C[M][N] (+)= A[M][Kin] * B[Kin][N]
// 64x64 tile, BK=16, 256 threads, 4x4 microtile
// ---------------------------------------------------------------------------
__global__ void gemm_nn(const float* __restrict__ A, int lda, long sA,
                        const float* __restrict__ Bm, int ldb, long sB,
                        float* __restrict__ Cm, int ldc, long sC,
                        int M, int N, int Kin, int accum)
{
    __shared__ float As[16][65];
    __shared__ float Bs[16][65];
    const float* Ab = A  + (long)blockIdx.z * sA;
    const float* Bb = Bm + (long)blockIdx.z * sB;
    float*       Cb = Cm + (long)blockIdx.z * sC;
    int m0 = blockIdx.y * 64, n0 = blockIdx.x * 64;
    int tid = threadIdx.x;
    int tx = tid & 15, ty = tid >> 4;
    float acc[4][4] = {};

    for (int k0 = 0; k0 < Kin; k0 += 16) {
        // A tile: 64 rows(m) x 16 cols(k), coalesced along k
        #pragma unroll
        for (int j = 0; j < 4; j++) {
            int i = tid + j * 256;
            int m = i >> 4, k = i & 15;
            float v = 0.f;
            if (m0 + m < M && k0 + k < Kin) v = Ab[(long)(m0 + m) * lda + k0 + k];
            As[k][m] = v;
        }
        // B tile: 16 rows(k) x 64 cols(n), coalesced along n
        #pragma unroll
        for (int j = 0; j < 4; j++) {
            int i = tid + j * 256;
            int k = i >> 6, n = i & 63;
            float v = 0.f;
            if (k0 + k < Kin && n0 + n < N) v = Bb[(long)(k0 + k) * ldb + n0 + n];
            Bs[k][n] = v;
        }
        __syncthreads();
        #pragma unroll
        for (int kk = 0; kk < 16; kk++) {
            float a[4], b[4];
            #pragma unroll
            for (int i = 0; i < 4; i++) a[i] = As[kk][ty + 16 * i];
            #pragma unroll
            for (int j = 0; j < 4; j++) b[j] = Bs[kk][tx + 16 * j];
            #pragma unroll
            for (int i = 0; i < 4; i++)
                #pragma unroll
                for (int j = 0; j < 4; j++)
                    acc[i][j] += a[i] * b[j];
        }
        __syncthreads();
    }

    #pragma unroll
    for (int i = 0; i < 4; i++) {
        int m = m0 + ty + 16 * i;
        if (m >= M) continue;
        #pragma unroll
        for (int j = 0; j < 4; j++) {
            int n = n0 + tx + 16 * j;
            if (n >= N) continue;
            long idx = (long)m * ldc + n;
            Cb[idx] = acc[i][j] + (accum ? Cb[idx] : 0.f);
        }
    }
}

// ---------------------------------------------------------------------------
// NT GEMM:  C[M][N] (+)= A[M][Kin] * B[N][Kin]   (both row-major, inner Kin)
// ---------------------------------------------------------------------------
__global__ void gemm_nt(const float* __restrict__ A, int lda, long sA,
                        const float* __restrict__ Bm, int ldb, long sB,
                        float* __restrict__ Cm, int ldc, long sC,
                        int M, int N, int Kin, int accum)
{
    __shared__ float As[16][65];
    __shared__ float Bs[16][65];
    const float* Ab = A  + (long)blockIdx.z * sA;
    const float* Bb = Bm + (long)blockIdx.z * sB;
    float*       Cb = Cm + (long)blockIdx.z * sC;
    int m0 = blockIdx.y * 64, n0 = blockIdx.x * 64;
    int tid = threadIdx.x;
    int tx = tid & 15, ty = tid >> 4;
    float acc[4][4] = {};

    for (int k0 = 0; k0 < Kin; k0 += 16) {
        #pragma unroll
        for (int j = 0; j < 4; j++) {
            int i = tid + j * 256;
            int m = i >> 4, k = i & 15;
            float v = 0.f;
            if (m0 + m < M && k0 + k < Kin) v = Ab[(long)(m0 + m) * lda + k0 + k];
            As[k][m] = v;
        }
        #pragma unroll
        for (int j = 0; j < 4; j++) {
            int i = tid + j * 256;
            int n = i >> 4, k = i & 15;
            float v = 0.f;
            if (n0 + n < N && k0 + k < Kin) v = Bb[(long)(n0 + n) * ldb + k0 + k];
            Bs[k][n] = v;
        }
        __syncthreads();
        #pragma unroll
        for (int kk = 0; kk < 16; kk++) {
            float a[4], b[4];
            #pragma unroll
            for (int i = 0; i < 4; i++) a[i] = As[kk][ty + 16 * i];
            #pragma unroll
            for (int j = 0; j < 4; j++) b[j] = Bs[kk][tx + 16 * j];
            #pragma unroll
            for (int i = 0; i < 4; i++)
                #pragma unroll
                for (int j = 0; j < 4; j++)
                    acc[i][j] += a[i] * b[j];
        }
        __syncthreads();
    }

    #pragma unroll
    for (int i = 0; i < 4; i++) {
        int m = m0 + ty + 16 * i;
        if (m >= M) continue;
        #pragma unroll
        for (int j = 0; j < 4; j++) {
            int n = n0 + tx + 16 * j;
            if (n >= N) continue;
            long idx = (long)m * ldc + n;
            Cb[idx] = acc[i][j] + (accum ? Cb[idx] : 0.f);
        }
    }
}

// ---------------------------------------------------------------------------
// Softmax over n (16384) per (b,k) row. One block per row.
// ---------------------------------------------------------------------------
__global__ void softmax_rows(const float* __restrict__ in, float* __restrict__ out)
{
    __shared__ float red[256];
    long base = (long)blockIdx.x * N_;
    int tid = threadIdx.x;

    float mx = -1e30f;
    for (int i = tid; i < N_; i += 256) mx = fmaxf(mx, in[base + i]);
    red[tid] = mx; __syncthreads();
    for (int s = 128; s > 0; s >>= 1) {
        if (tid < s) red[tid] = fmaxf(red[tid], red[tid + s]);
        __syncthreads();
    }
    mx = red[0]; __syncthreads();

    float sum = 0.f;
    for (int i = tid; i < N_; i += 256) sum += expf(in[base + i] - mx);
    red[tid] = sum; __syncthreads();
    for (int s = 128; s > 0; s >>= 1) {
        if (tid < s) red[tid] += red[tid + s];
        __syncthreads();
    }
    float inv = 1.f / red[0];

    for (int i = tid; i < N_; i += 256) out[base + i] = expf(in[base + i] - mx) * inv;
}

// ---------------------------------------------------------------------------
// Softmax over k (150) per (b,n) column. Thread-per-n, coalesced.
// ---------------------------------------------------------------------------
__global__ void softmax_cols(const float* __restrict__ in, float* __restrict__ out)
{
    int n = blockIdx.x * blockDim.x + threadIdx.x;
    int b = blockIdx.y;
    long base = (long)b * K_ * N_ + n;

    float mx = -1e30f;
    for (int k = 0; k < K_; k++) mx = fmaxf(mx, in[base + (long)k * N_]);
    float s = 0.f;
    for (int k = 0; k < K_; k++) s += expf(in[base + (long)k * N_] - mx);
    float inv = 1.f / s;
    for (int k = 0; k < K_; k++)
        out[base + (long)k * N_] = expf(in[base + (long)k * N_] - mx) * inv;
}

// ---------------------------------------------------------------------------
// LayerNorm over k (150) per (b,n); writes output in [b][k][n] layout.
// ---------------------------------------------------------------------------
__global__ void layernorm_k(const float* __restrict__ m,
                            const float* __restrict__ gamma,
                            const float* __restrict__ beta,
                            float* __restrict__ out)
{
    int n = blockIdx.x * blockDim.x + threadIdx.x;
    int b = blockIdx.y;
    long base = (long)b * K_ * N_ + n;

    float mu = 0.f;
    for (int k = 0; k < K_; k++) mu += m[base + (long)k * N_];
    mu *= (1.f / K_);
    float var = 0.f;
    for (int k = 0; k < K_; k++) {
        float d = m[base + (long)k * N_] - mu;
        var += d * d;
    }
    var *= (1.f / K_);
    float r = rsqrtf(var + 1e-5f);
    for (int k = 0; k < K_; k++) {
        float v = (m[base + (long)k * N_] - mu) * r;
        out[base + (long)k * N_] = v * __ldg(&gamma[k]) + __ldg(&beta[k]);
    }
}

// ---------------------------------------------------------------------------
// Broadcast cls_repr [K,C] to g_acls [B,K,C] (bias init for aligned_cls)
// ---------------------------------------------------------------------------
__global__ void bcast_cls(const float* __restrict__ cls, float* __restrict__ dst)
{
    int i = blockIdx.x * blockDim.x + threadIdx.x;
    if (i < B_ * K_ * C_) dst[i] = cls[i % (K_ * C_)];
}

// ---------------------------------------------------------------------------
// kernel_launch
// Inputs: 0:x [8,512,128,128] 1:cls_repr [1,150,512] 2:W_cls [512,512]
//         3:W_feat [512,512]  4:ln_gamma [150]       5:ln_beta [150]
// Output: [8,150,128,128] fp32
// ---------------------------------------------------------------------------
extern "C" void kernel_launch(void* const* d_in, const int* in_sizes, int n_in,
                              void* d_out, int out_size)
{
    const float* x     = (const float*)d_in[0];
    const float* cls   = (const float*)d_in[1];
    const float* W_cls = (const float*)d_in[2];
    const float* W_feat= (const float*)d_in[3];
    const float* gamma = (const float*)d_in[4];
    const float* beta  = (const float*)d_in[5];
    float* out = (float*)d_out;

    float *attn, *clsA, *posA, *P, *acls, *M2, *ST;
    cudaGetSymbolAddress((void**)&attn, g_attn);
    cudaGetSymbolAddress((void**)&clsA, g_cls_attn);
    cudaGetSymbolAddress((void**)&posA, g_pos_attn);
    cudaGetSymbolAddress((void**)&P,    g_P);
    cudaGetSymbolAddress((void**)&acls, g_acls);
    cudaGetSymbolAddress((void**)&M2,   g_M2);
    cudaGetSymbolAddress((void**)&ST,   g_ST);

    const long sX = (long)C_ * N_;     // x batch stride
    const long sA = (long)K_ * N_;     // attn batch stride
    const long sP = (long)K_ * C_;     // P / acls batch stride
    const long sS = (long)K_ * K_;     // ST batch stride

    // M2[k][d] = sum_c cls[k][c] * W_feat[d][c]
    gemm_nt<<<dim3(8, 3, 1), 256>>>(cls, C_, 0, W_feat, C_, 0,
                                    M2, C_, 0, K_, C_, C_, 0);

    // coupled_attn[b][k][n] = sum_c cls[k][c] * x[b][c][n]
    gemm_nn<<<dim3(N_ / 64, 3, B_), 256>>>(cls, C_, 0, x, N_, sX,
                                           attn, N_, sA, K_, N_, C_, 0);

    // softmaxes
    softmax_rows<<<B_ * K_, 256>>>(attn, clsA);
    softmax_cols<<<dim3(N_ / 256, B_), 256>>>(attn, posA);

    // P[b][k][c] = sum_n cls_attn[b][k][n] * x[b][c][n]
    gemm_nt<<<dim3(8, 3, B_), 256>>>(clsA, N_, sA, x, N_, sX,
                                     P, C_, sP, K_, C_, N_, 0);

    // aligned_cls = cls + P @ W_cls^T
    bcast_cls<<<(B_ * K_ * C_ + 255) / 256, 256>>>(cls, acls);
    gemm_nt<<<dim3(8, 3, B_), 256>>>(P, C_, sP, W_cls, C_, 0,
                                     acls, C_, sP, K_, C_, C_, 1);

    // ST[b][k'][k] = sum_d acls[b][k'][d] * M2[k][d]
    gemm_nt<<<dim3(3, 3, B_), 256>>>(acls, C_, sP, M2, C_, 0,
                                     ST, K_, sS, K_, K_, C_, 0);

    // masks[b][k'][n] = sum_c acls[k'][c]*x[b][c][n]  (reuse attn buffer)
    gemm_nn<<<dim3(N_ / 64, 3, B_), 256>>>(acls, C_, sP, x, N_, sX,
                                           attn, N_, sA, K_, N_, C_, 0);
    //              += sum_k ST[k'][k]*pos_attn[b][k][n]
    gemm_nn<<<dim3(N_ / 64, 3, B_), 256>>>(ST, K_, sS, posA, N_, sA,
                                           attn, N_, sA, K_, N_, K_, 1);

    // LayerNorm over k', write [b][k'][n]
    layernorm_k<<<dim3(N_ / 256, B_), 256>>>(attn, gamma, beta, out);
}

// round 4
// speedup vs baseline: 3.5805x; 3.5805x over previous
#include <cuda_runtime.h>
#include <cstdint>

// Problem constants
#define B_  8
#define C_  512          // channels == D
#define N_  16384        // H*W
#define K_  150          // num classes
#define NSPLIT 8         // split-K for the P gemm

// ---------------------------------------------------------------------------
// Device scratch
// ---------------------------------------------------------------------------
__device__ float g_attn    [B_ * K_ * N_];
__device__ float g_cls_attn[B_ * K_ * N_];
__device__ float g_pos_attn[B_ * K_ * N_];
__device__ float g_P       [B_ * K_ * C_];
__device__ float g_Ppart   [NSPLIT * B_ * K_ * C_];
__device__ float g_acls    [B_ * K_ * C_];
__device__ float g_M2      [K_ * C_];
__device__ float g_ST      [B_ * K_ * K_];

// ---------------------------------------------------------------------------
// tf32 helpers
// ---------------------------------------------------------------------------
__device__ __forceinline__ uint32_t f2tf(float f) {
    uint32_t u;
    asm("cvt.rna.tf32.f32 %0, %1;" : "=r"(u) : "f"(f));
    return u;
}

__device__ __forceinline__ void mma8(float* c,
                                     uint32_t a0, uint32_t a1, uint32_t a2, uint32_t a3,
                                     uint32_t b0, uint32_t b1) {
    asm("mma.sync.aligned.m16n8k8.row.col.f32.tf32.tf32.f32 "
        "{%0,%1,%2,%3}, {%4,%5,%6,%7}, {%8,%9}, {%0,%1,%2,%3};"
        : "+f"(c[0]), "+f"(c[1]), "+f"(c[2]), "+f"(c[3])
        : "r"(a0), "r"(a1), "r"(a2), "r"(a3), "r"(b0), "r"(b1));
}

// Tile config (shared by both mma kernels)
#define BM  128   // m tile (pixels in k1, channels in k2)
#define BN  80    // n tile (classes; 2 blocks cover 150 padded to 160)
#define BK  32
#define BMp 136   // BM pad: 136 mod 32 == 8 -> conflict-free [k][m] frag reads
#define BKp 36    // BK pad: 36  mod 32 == 4 -> conflict-free [n][k] frag reads

// ---------------------------------------------------------------------------
// k1_tall: Out[b][n_cls][pix] = A1[b]·B1[b] (+ A2[b]·B2[b] fused)
//   A*: [K_][Kin*] row-major (class operand, k-inner -> native B fragment)
//   B*: [Kin*][N_] row-major (x-like operand, staged transposed in smem)
// mma orientation: m = pixel, n = class.
// grid = (N_/BM, 2, B_), block = 256
// ---------------------------------------------------------------------------
__global__ __launch_bounds__(256) void k1_tall(
    const float* __restrict__ A1, long sA1, const float* __restrict__ B1, long sB1, int Kin1,
    const float* __restrict__ A2, long sA2, const float* __restrict__ B2, long sB2, int Kin2,
    float* __restrict__ Out, long sO)
{
    __shared__ uint32_t sm[BN * BMp];            // 10880 words = 43.5 KB
    uint32_t* As = sm;                           // [BK][BMp]  (k-major, transposed x)
    uint32_t* Bs = sm + BK * BMp;                // [BN][BKp]  (classes)
    float*    Cs = (float*)sm;                   // [BN][BMp]  epilogue staging (aliases)

    const int tid  = threadIdx.x;
    const int lane = tid & 31, warp = tid >> 5;
    const int wm = (warp & 3) * 32;              // warp m offset (4 warps over m)
    const int wn = (warp >> 2) * 40;             // warp n offset (2 warps over n)
    const int m0 = blockIdx.x * BM;
    const int n0 = blockIdx.y * BN;
    const int b  = blockIdx.z;

    float acc[2][5][4];
    #pragma unroll
    for (int i = 0; i < 2; i++)
        #pragma unroll
        for (int j = 0; j < 5; j++)
            #pragma unroll
            for (int q = 0; q < 4; q++) acc[i][j][q] = 0.f;

    for (int ph = 0; ph < 2; ph++) {
        const int Kin = (ph == 0) ? Kin1 : Kin2;
        if (Kin == 0) continue;
        const float* Ag = (ph == 0) ? (A1 + (long)b * sA1) : (A2 + (long)b * sA2);
        const float* Bg = (ph == 0) ? (B1 + (long)b * sB1) : (B2 + (long)b * sB2);

        for (int k0 = 0; k0 < Kin; k0 += BK) {
            // --- As[k][m]: 32 k-rows x 128 pixels, float4, row-level k guard ---
            #pragma unroll
            for (int p = 0; p < 4; p++) {
                int r  = warp + p * 8;          // k row 0..31
                int c4 = lane * 4;              // pixel col
                uint32_t v0 = 0, v1 = 0, v2 = 0, v3 = 0;
                if (k0 + r < Kin) {
                    const float4 f = *(const float4*)(Bg + (long)(k0 + r) * N_ + m0 + c4);
                    v0 = f2tf(f.x); v1 = f2tf(f.y); v2 = f2tf(f.z); v3 = f2tf(f.w);
                }
                *(uint4*)(As + r * BMp + c4) = make_uint4(v0, v1, v2, v3);
            }
            // --- Bs[n][k]: 80 class-rows x 32 k, scalar with full guards ---
            #pragma unroll
            for (int p = 0; p < 10; p++) {
                int idx = tid + p * 256;        // BN*BK = 2560 exactly
                int n  = idx >> 5;
                int kk = idx & 31;
                int g  = n0 + n;
                float v = 0.f;
                if (g < K_ && k0 + kk < Kin) v = Ag[(long)g * Kin + k0 + kk];
                Bs[n * BKp + kk] = f2tf(v);
            }
            __syncthreads();

            #pragma unroll
            for (int ks = 0; ks < 4; ks++) {
                uint32_t a[2][4], bb[5][2];
                const int kc = ks * 8 + (lane & 3);
                #pragma unroll
                for (int mi = 0; mi < 2; mi++) {
                    int mr = wm + mi * 16 + (lane >> 2);
                    a[mi][0] = As[kc * BMp + mr];
                    a[mi][1] = As[kc * BMp + mr + 8];
                    a[mi][2] = As[(kc + 4) * BMp + mr];
                    a[mi][3] = As[(kc + 4) * BMp + mr + 8];
                }
                #pragma unroll
                for (int ni = 0; ni < 5; ni++) {
                    int nc = wn + ni * 8 + (lane >> 2);
                    bb[ni][0] = Bs[nc * BKp + kc];
                    bb[ni][1] = Bs[nc * BKp + kc + 4];
                }
                #pragma unroll
                for (int mi = 0; mi < 2; mi++)
                    #pragma unroll
                    for (int ni = 0; ni < 5; ni++)
                        mma8(acc[mi][ni], a[mi][0], a[mi][1], a[mi][2], a[mi][3],
                             bb[ni][0], bb[ni][1]);
            }
            __syncthreads();
        }
    }

    // --- epilogue: transpose-stage to Cs[n][m], then coalesced [class][pix] writes ---
    #pragma unroll
    for (int mi = 0; mi < 2; mi++)
        #pragma unroll
        for (int ni = 0; ni < 5; ni++) {
            int mr = wm + mi * 16 + (lane >> 2);
            int nc = wn + ni * 8 + (lane & 3) * 2;
            Cs[ nc      * BMp + mr    ] = acc[mi][ni][0];
            Cs[(nc + 1) * BMp + mr    ] = acc[mi][ni][1];
            Cs[ nc      * BMp + mr + 8] = acc[mi][ni][2];
            Cs[(nc + 1) * BMp + mr + 8] = acc[mi][ni][3];
        }
    __syncthreads();

    float* Ob = Out + (long)b * sO;
    #pragma unroll
    for (int i = 0; i < 10; i++) {
        int r = warp + i * 8;
        int g = n0 + r;
        if (g < K_) {
            float4 v = *(float4*)(Cs + r * BMp + lane * 4);
            *(float4*)(Ob + (long)g * N_ + m0 + lane * 4) = v;
        }
    }
}

// ---------------------------------------------------------------------------
// k2_pgemm: Ppart[split][b][class][c] = sum_{pix in split} clsA[b][class][pix]*x[b][c][pix]
// mma orientation: m = channel c, n = class; both operands natively k-inner.
// grid = (8 [mblk*nblk], NSPLIT, B_), block = 256
// ---------------------------------------------------------------------------
#define CHUNK (N_ / NSPLIT)   // 2048

__global__ __launch_bounds__(256) void k2_pgemm(
    const float* __restrict__ Xg,   // [b][C_][N_]
    const float* __restrict__ Wg,   // clsA [b][K_][N_]
    float* __restrict__ Pp)         // [NSPLIT][b][K_][C_]
{
    __shared__ uint32_t sm[BN * BMp];
    uint32_t* As = sm;                  // [BM][BKp] = 4608
    uint32_t* Bs = sm + BM * BKp;       // [BN][BKp] = 2880
    float*    Cs = (float*)sm;          // [BN][BMp] epilogue

    const int tid  = threadIdx.x;
    const int lane = tid & 31, warp = tid >> 5;
    const int wm = (warp & 3) * 32, wn = (warp >> 2) * 40;
    const int mblk = blockIdx.x & 3, nblk = blockIdx.x >> 2;
    const int m0 = mblk * BM;           // channel offset
    const int n0 = nblk * BN;           // class offset
    const int split = blockIdx.y;
    const int b = blockIdx.z;

    const float* Xb = Xg + (long)b * C_ * N_;
    const float* Wb = Wg + (long)b * K_ * N_;

    float acc[2][5][4];
    #pragma unroll
    for (int i = 0; i < 2; i++)
        #pragma unroll
        for (int j = 0; j < 5; j++)
            #pragma unroll
            for (int q = 0; q < 4; q++) acc[i][j][q] = 0.f;

    const int kbeg = split * CHUNK;
    for (int k0 = kbeg; k0 < kbeg + CHUNK; k0 += BK) {
        // As[m][k]: 128 channel-rows x 32 pix, float4 (no guards: chunk interior)
        #pragma unroll
        for (int p = 0; p < 4; p++) {
            int f4 = tid + p * 256;              // 1024 float4
            int r  = f4 >> 3;
            int c4 = (f4 & 7) * 4;
            const float4 f = *(const float4*)(Xb + (long)(m0 + r) * N_ + k0 + c4);
            *(uint4*)(As + r * BKp + c4) =
                make_uint4(f2tf(f.x), f2tf(f.y), f2tf(f.z), f2tf(f.w));
        }
        // Bs[n][k]: 80 class-rows x 32 pix, float4, row guard on class
        #pragma unroll
        for (int p = 0; p < 3; p++) {
            int f4 = tid + p * 256;              // 640 float4
            if (f4 < BN * 8) {
                int r  = f4 >> 3;
                int c4 = (f4 & 7) * 4;
                int g  = n0 + r;
                uint32_t v0 = 0, v1 = 0, v2 = 0, v3 = 0;
                if (g < K_) {
                    const float4 f = *(const float4*)(Wb + (long)g * N_ + k0 + c4);
                    v0 = f2tf(f.x); v1 = f2tf(f.y); v2 = f2tf(f.z); v3 = f2tf(f.w);
                }
                *(uint4*)(Bs + r * BKp + c4) = make_uint4(v0, v1, v2, v3);
            }
        }
        __syncthreads();

        #pragma unroll
        for (int ks = 0; ks < 4; ks++) {
            uint32_t a[2][4], bb[5][2];
            const int kc = ks * 8 + (lane & 3);
            #pragma unroll
            for (int mi = 0; mi < 2; mi++) {
                int mr = wm + mi * 16 + (lane >> 2);
                a[mi][0] = As[ mr      * BKp + kc];
                a[mi][1] = As[(mr + 8) * BKp + kc];
                a[mi][2] = As[ mr      * BKp + kc + 4];
                a[mi][3] = As[(mr + 8) * BKp + kc + 4];
            }
            #pragma unroll
            for (int ni = 0; ni < 5; ni++) {
                int nc = wn + ni * 8 + (lane >> 2);
                bb[ni][0] = Bs[nc * BKp + kc];
                bb[ni][1] = Bs[nc * BKp + kc + 4];
            }
            #pragma unroll
            for (int mi = 0; mi < 2; mi++)
                #pragma unroll
                for (int ni = 0; ni < 5; ni++)
                    mma8(acc[mi][ni], a[mi][0], a[mi][1], a[mi][2], a[mi][3],
                         bb[ni][0], bb[ni][1]);
        }
        __syncthreads();
    }

    // epilogue -> Cs[n][m] -> Ppart[split][b][class][c]
    #pragma unroll
    for (int mi = 0; mi < 2; mi++)
        #pragma unroll
        for (int ni = 0; ni < 5; ni++) {
            int mr = wm + mi * 16 + (lane >> 2);
            int nc = wn + ni * 8 + (lane & 3) * 2;
            Cs[ nc      * BMp + mr    ] = acc[mi][ni][0];
            Cs[(nc + 1) * BMp + mr    ] = acc[mi][ni][1];
            Cs[ nc      * BMp + mr + 8] = acc[mi][ni][2];
            Cs[(nc + 1) * BMp + mr + 8] = acc[mi][ni][3];
        }
    __syncthreads();

    float* Pb = Pp + ((long)split * B_ + b) * K_ * C_;
    #pragma unroll
    for (int i = 0; i < 10; i++) {
        int r = warp + i * 8;
        int g = n0 + r;
        if (g < K_) {
            float4 v = *(float4*)(Cs + r * BMp + lane * 4);
            *(float4*)(Pb + (long)g * C_ + m0 + lane * 4) = v;
        }
    }
}

// ---------------------------------------------------------------------------
// reduce split-K partials: P = sum_s Ppart[s]
// ---------------------------------------------------------------------------
__global__ void reduce_P(const float* __restrict__ Pp, float* __restrict__ P)
{
    int i = blockIdx.x * blockDim.x + threadIdx.x;
    if (i < B_ * K_ * C_) {
        float s = 0.f;
        #pragma unroll
        for (int sp = 0; sp < NSPLIT; sp++) s += Pp[(long)sp * B_ * K_ * C_ + i];
        P[i] = s;
    }
}

// ---------------------------------------------------------------------------
// SIMT NT GEMM for the small matmuls (M2, acls-update, ST): C (+)= A * B^T
// ---------------------------------------------------------------------------
__global__ void gemm_nt(const float* __restrict__ A, int lda, long sA,
                        const float* __restrict__ Bm, int ldb, long sB,
                        float* __restrict__ Cm, int ldc, long sC,
                        int M, int N, int Kin, int accum)
{
    __shared__ float As[16][65];
    __shared__ float Bs[16][65];
    const float* Ab = A  + (long)blockIdx.z * sA;
    const float* Bb = Bm + (long)blockIdx.z * sB;
    float*       Cb = Cm + (long)blockIdx.z * sC;
    int m0 = blockIdx.y * 64, n0 = blockIdx.x * 64;
    int tid = threadIdx.x;
    int tx = tid & 15, ty = tid >> 4;
    float acc[4][4] = {};

    for (int k0 = 0; k0 < Kin; k0 += 16) {
        #pragma unroll
        for (int j = 0; j < 4; j++) {
            int i = tid + j * 256;
            int m = i >> 4, k = i & 15;
            float v = 0.f;
            if (m0 + m < M && k0 + k < Kin) v = Ab[(long)(m0 + m) * lda + k0 + k];
            As[k][m] = v;
        }
        #pragma unroll
        for (int j = 0; j < 4; j++) {
            int i = tid + j * 256;
            int n = i >> 4, k = i & 15;
            float v = 0.f;
            if (n0 + n < N && k0 + k < Kin) v = Bb[(long)(n0 + n) * ldb + k0 + k];
            Bs[k][n] = v;
        }
        __syncthreads();
        #pragma unroll
        for (int kk = 0; kk < 16; kk++) {
            float a[4], b[4];
            #pragma unroll
            for (int i = 0; i < 4; i++) a[i] = As[kk][ty + 16 * i];
            #pragma unroll
            for (int j = 0; j < 4; j++) b[j] = Bs[kk][tx + 16 * j];
            #pragma unroll
            for (int i = 0; i < 4; i++)
                #pragma unroll
                for (int j = 0; j < 4; j++)
                    acc[i][j] += a[i] * b[j];
        }
        __syncthreads();
    }

    #pragma unroll
    for (int i = 0; i < 4; i++) {
        int m = m0 + ty + 16 * i;
        if (m >= M) continue;
        #pragma unroll
        for (int j = 0; j < 4; j++) {
            int n = n0 + tx + 16 * j;
            if (n >= N) continue;
            long idx = (long)m * ldc + n;
            Cb[idx] = acc[i][j] + (accum ? Cb[idx] : 0.f);
        }
    }
}

// ---------------------------------------------------------------------------
// Softmax over n (16384) per (b,k) row
// ---------------------------------------------------------------------------
__global__ void softmax_rows(const float* __restrict__ in, float* __restrict__ out)
{
    __shared__ float red[256];
    long base = (long)blockIdx.x * N_;
    int tid = threadIdx.x;

    float mx = -1e30f;
    for (int i = tid; i < N_; i += 256) mx = fmaxf(mx, in[base + i]);
    red[tid] = mx; __syncthreads();
    for (int s = 128; s > 0; s >>= 1) {
        if (tid < s) red[tid] = fmaxf(red[tid], red[tid + s]);
        __syncthreads();
    }
    mx = red[0]; __syncthreads();

    float sum = 0.f;
    for (int i = tid; i < N_; i += 256) sum += expf(in[base + i] - mx);
    red[tid] = sum; __syncthreads();
    for (int s = 128; s > 0; s >>= 1) {
        if (tid < s) red[tid] += red[tid + s];
        __syncthreads();
    }
    float inv = 1.f / red[0];

    for (int i = tid; i < N_; i += 256) out[base + i] = expf(in[base + i] - mx) * inv;
}

// ---------------------------------------------------------------------------
// Softmax over k (150) per (b,n) column
// ---------------------------------------------------------------------------
__global__ void softmax_cols(const float* __restrict__ in, float* __restrict__ out)
{
    int n = blockIdx.x * blockDim.x + threadIdx.x;
    int b = blockIdx.y;
    long base = (long)b * K_ * N_ + n;

    float mx = -1e30f;
    for (int k = 0; k < K_; k++) mx = fmaxf(mx, in[base + (long)k * N_]);
    float s = 0.f;
    for (int k = 0; k < K_; k++) s += expf(in[base + (long)k * N_] - mx);
    float inv = 1.f / s;
    for (int k = 0; k < K_; k++)
        out[base + (long)k * N_] = expf(in[base + (long)k * N_] - mx) * inv;
}

// ---------------------------------------------------------------------------
// LayerNorm over k (150) per (b,n)
// ---------------------------------------------------------------------------
__global__ void layernorm_k(const float* __restrict__ m,
                            const float* __restrict__ gamma,
                            const float* __restrict__ beta,
                            float* __restrict__ out)
{
    int n = blockIdx.x * blockDim.x + threadIdx.x;
    int b = blockIdx.y;
    long base = (long)b * K_ * N_ + n;

    float mu = 0.f;
    for (int k = 0; k < K_; k++) mu += m[base + (long)k * N_];
    mu *= (1.f / K_);
    float var = 0.f;
    for (int k = 0; k < K_; k++) {
        float d = m[base + (long)k * N_] - mu;
        var += d * d;
    }
    var *= (1.f / K_);
    float r = rsqrtf(var + 1e-5f);
    for (int k = 0; k < K_; k++) {
        float v = (m[base + (long)k * N_] - mu) * r;
        out[base + (long)k * N_] = v * __ldg(&gamma[k]) + __ldg(&beta[k]);
    }
}

__global__ void bcast_cls(const float* __restrict__ cls, float* __restrict__ dst)
{
    int i = blockIdx.x * blockDim.x + threadIdx.x;
    if (i < B_ * K_ * C_) dst[i] = cls[i % (K_ * C_)];
}

// ---------------------------------------------------------------------------
// kernel_launch
// ---------------------------------------------------------------------------
extern "C" void kernel_launch(void* const* d_in, const int* in_sizes, int n_in,
                              void* d_out, int out_size)
{
    const float* x      = (const float*)d_in[0];
    const float* cls    = (const float*)d_in[1];
    const float* W_cls  = (const float*)d_in[2];
    const float* W_feat = (const float*)d_in[3];
    const float* gamma  = (const float*)d_in[4];
    const float* beta   = (const float*)d_in[5];
    float* out = (float*)d_out;

    float *attn, *clsA, *posA, *P, *Ppart, *acls, *M2, *ST;
    cudaGetSymbolAddress((void**)&attn,  g_attn);
    cudaGetSymbolAddress((void**)&clsA,  g_cls_attn);
    cudaGetSymbolAddress((void**)&posA,  g_pos_attn);
    cudaGetSymbolAddress((void**)&P,     g_P);
    cudaGetSymbolAddress((void**)&Ppart, g_Ppart);
    cudaGetSymbolAddress((void**)&acls,  g_acls);
    cudaGetSymbolAddress((void**)&M2,    g_M2);
    cudaGetSymbolAddress((void**)&ST,    g_ST);

    const long sX = (long)C_ * N_;
    const long sA = (long)K_ * N_;
    const long sP = (long)K_ * C_;
    const long sS = (long)K_ * K_;

    // M2[k][d] = sum_c cls[k][c] * W_feat[d][c]   (small, SIMT fp32)
    gemm_nt<<<dim3(8, 3, 1), 256>>>(cls, C_, 0, W_feat, C_, 0,
                                    M2, C_, 0, K_, C_, C_, 0);

    // coupled_attn[b][k][n] = sum_c cls[k][c]*x[b][c][n]   (tf32 mma)
    k1_tall<<<dim3(N_ / BM, 2, B_), 256>>>(cls, 0, x, sX, C_,
                                           nullptr, 0, nullptr, 0, 0,
                                           attn, sA);

    // softmaxes
    softmax_rows<<<B_ * K_, 256>>>(attn, clsA);
    softmax_cols<<<dim3(N_ / 256, B_), 256>>>(attn, posA);

    // P[b][k][c] = sum_n clsA[b][k][n]*x[b][c][n]   (tf32 mma, split-K)
    k2_pgemm<<<dim3(8, NSPLIT, B_), 256>>>(x, clsA, Ppart);
    reduce_P<<<(B_ * K_ * C_ + 255) / 256, 256>>>(Ppart, P);

    // aligned_cls = cls + P @ W_cls^T   (small, SIMT fp32)
    bcast_cls<<<(B_ * K_ * C_ + 255) / 256, 256>>>(cls, acls);
    gemm_nt<<<dim3(8, 3, B_), 256>>>(P, C_, sP, W_cls, C_, 0,
                                     acls, C_, sP, K_, C_, C_, 1);

    // ST[b][k'][k] = sum_d acls[b][k'][d]*M2[k][d]   (small, SIMT fp32)
    gemm_nt<<<dim3(3, 3, B_), 256>>>(acls, C_, sP, M2, C_, 0,
                                     ST, K_, sS, K_, K_, C_, 0);

    // masks[b][k'][n] = acls·x + ST·posA   (fused tf32 mma, reuse attn buffer)
    k1_tall<<<dim3(N_ / BM, 2, B_), 256>>>(acls, sP, x, sX, C_,
                                           ST, sS, posA, sA, K_,
                                           attn, sA);

    // LayerNorm over k', write [b][k'][n]
    layernorm_k<<<dim3(N_ / 256, B_), 256>>>(attn, gamma, beta, out);
}

// round 5
// speedup vs baseline: 4.8643x; 1.3585x over previous
#include <cuda_runtime.h>
#include <cstdint>

// Problem constants
#define B_  8
#define C_  512          // channels == D
#define N_  16384        // H*W
#define K_  150          // num classes
#define NSPLIT 8         // split-K for the P gemm
#define CHUNK (N_ / NSPLIT)

// Tile config
#define BM  128   // m tile (pixels in k_attn/k_masks, channels in k2)
#define BN  160   // n tile: covers all 150 classes (padded)
#define BK  32
#define BMp 136   // 136 mod 32 == 8 -> conflict-free [k][m] frag reads
#define BKp 36    // 36  mod 32 == 4 -> conflict-free [n][k] frag reads

// smem (words): mainloop As/Bs; epilogue Cs aliases from 0
#define SMEM_ATTN_W  (BN * BMp)            // 21760 words = 87040 B
#define SMEM_K2_W    (BN * BMp)            // rs stats live inside mainloop region
#define SMEM_MASK_W  (BN * BMp + 256)      // + mu/rstd arrays = 22016 words

// ---------------------------------------------------------------------------
// Device scratch
// ---------------------------------------------------------------------------
__device__ float g_attn [B_ * K_ * N_];
__device__ float g_P    [B_ * K_ * C_];
__device__ float g_Ppart[NSPLIT * B_ * K_ * C_];
__device__ float g_acls [B_ * K_ * C_];
__device__ float g_M2   [K_ * C_];
__device__ float g_ST   [B_ * K_ * K_];
__device__ float g_cmx  [B_ * N_];
__device__ float g_cinv [B_ * N_];
__device__ float g_rmx  [B_ * K_];
__device__ float g_rinv [B_ * K_];

// ---------------------------------------------------------------------------
// tf32 helpers
// ---------------------------------------------------------------------------
__device__ __forceinline__ uint32_t f2tf(float f) {
    uint32_t u;
    asm("cvt.rna.tf32.f32 %0, %1;" : "=r"(u) : "f"(f));
    return u;
}

__device__ __forceinline__ void mma8(float* c,
                                     uint32_t a0, uint32_t a1, uint32_t a2, uint32_t a3,
                                     uint32_t b0, uint32_t b1) {
    asm("mma.sync.aligned.m16n8k8.row.col.f32.tf32.tf32.f32 "
        "{%0,%1,%2,%3}, {%4,%5,%6,%7}, {%8,%9}, {%0,%1,%2,%3};"
        : "+f"(c[0]), "+f"(c[1]), "+f"(c[2]), "+f"(c[3])
        : "r"(a0), "r"(a1), "r"(a2), "r"(a3), "r"(b0), "r"(b1));
}

// ---------------------------------------------------------------------------
// k_attn: attn[b][k][n] = sum_c cls[k][c]*x[b][c][n]; epilogue also emits
// per-pixel col-softmax stats (max over k, 1/sum exp).
// m = pixel (BM=128), n = class (BN=160 covers all 150).
// warp layout: 4(m) x 2(n); acc[2][10][4]. grid (N_/BM, 1, B_)
// ---------------------------------------------------------------------------
__global__ __launch_bounds__(256) void k_attn(
    const float* __restrict__ x, const float* __restrict__ cls,
    float* __restrict__ attn, float* __restrict__ cmx, float* __restrict__ cinv)
{
    extern __shared__ uint32_t sm[];
    uint32_t* As = sm;                 // [BK][BMp]
    uint32_t* Bs = sm + BK * BMp;      // [BN][BKp]
    float*    Cs = (float*)sm;         // [BN][BMp] epilogue alias

    const int tid = threadIdx.x, lane = tid & 31, warp = tid >> 5;
    const int wm = (warp & 3) * 32, wn = (warp >> 2) * 80;
    const int m0 = blockIdx.x * BM;
    const int b  = blockIdx.z;
    const float* Xb = x + (long)b * C_ * N_;

    float acc[2][10][4] = {};

    for (int k0 = 0; k0 < C_; k0 += BK) {
        #pragma unroll
        for (int p = 0; p < 4; p++) {                   // As[k][m] from x
            int r = warp + p * 8, c4 = lane * 4;
            const float4 f = *(const float4*)(Xb + (long)(k0 + r) * N_ + m0 + c4);
            *(uint4*)(As + r * BMp + c4) =
                make_uint4(f2tf(f.x), f2tf(f.y), f2tf(f.z), f2tf(f.w));
        }
        #pragma unroll
        for (int p = 0; p < 5; p++) {                   // Bs[n][k] from cls
            int f4 = tid + p * 256;
            int r = f4 >> 3, c4 = (f4 & 7) * 4;
            uint32_t v0 = 0, v1 = 0, v2 = 0, v3 = 0;
            if (r < K_) {
                const float4 f = *(const float4*)(cls + (long)r * C_ + k0 + c4);
                v0 = f2tf(f.x); v1 = f2tf(f.y); v2 = f2tf(f.z); v3 = f2tf(f.w);
            }
            *(uint4*)(Bs + r * BKp + c4) = make_uint4(v0, v1, v2, v3);
        }
        __syncthreads();
        #pragma unroll
        for (int ks = 0; ks < 4; ks++) {
            uint32_t a[2][4], bb[10][2];
            const int kc = ks * 8 + (lane & 3);
            #pragma unroll
            for (int mi = 0; mi < 2; mi++) {
                int mr = wm + mi * 16 + (lane >> 2);
                a[mi][0] = As[kc * BMp + mr];       a[mi][1] = As[kc * BMp + mr + 8];
                a[mi][2] = As[(kc + 4) * BMp + mr]; a[mi][3] = As[(kc + 4) * BMp + mr + 8];
            }
            #pragma unroll
            for (int ni = 0; ni < 10; ni++) {
                int nc = wn + ni * 8 + (lane >> 2);
                bb[ni][0] = Bs[nc * BKp + kc]; bb[ni][1] = Bs[nc * BKp + kc + 4];
            }
            #pragma unroll
            for (int mi = 0; mi < 2; mi++)
                #pragma unroll
                for (int ni = 0; ni < 10; ni++)
                    mma8(acc[mi][ni], a[mi][0], a[mi][1], a[mi][2], a[mi][3],
                         bb[ni][0], bb[ni][1]);
        }
        __syncthreads();
    }

    // stage to Cs[class][pixel]
    #pragma unroll
    for (int mi = 0; mi < 2; mi++)
        #pragma unroll
        for (int ni = 0; ni < 10; ni++) {
            int mr = wm + mi * 16 + (lane >> 2);
            int nc = wn + ni * 8 + (lane & 3) * 2;
            Cs[ nc      * BMp + mr    ] = acc[mi][ni][0];
            Cs[(nc + 1) * BMp + mr    ] = acc[mi][ni][1];
            Cs[ nc      * BMp + mr + 8] = acc[mi][ni][2];
            Cs[(nc + 1) * BMp + mr + 8] = acc[mi][ni][3];
        }
    __syncthreads();

    float* Ab = attn + (long)b * K_ * N_;
    #pragma unroll
    for (int i = 0; i < 19; i++) {
        int r = warp + i * 8;
        if (r < K_) {
            float4 v = *(float4*)(Cs + r * BMp + lane * 4);
            *(float4*)(Ab + (long)r * N_ + m0 + lane * 4) = v;
        }
    }
    // column softmax stats (over k per pixel)
    if (tid < BM) {
        float mx = -1e30f;
        for (int k = 0; k < K_; k++) mx = fmaxf(mx, Cs[k * BMp + tid]);
        float s = 0.f;
        for (int k = 0; k < K_; k++) s += expf(Cs[k * BMp + tid] - mx);
        cmx [(long)b * N_ + m0 + tid] = mx;
        cinv[(long)b * N_ + m0 + tid] = 1.f / s;
    }
}

// ---------------------------------------------------------------------------
// rowstats: per (b,k) row of attn -> max, 1/sum(exp). grid B_*K_
// ---------------------------------------------------------------------------
__global__ void rowstats(const float* __restrict__ in,
                         float* __restrict__ rmx, float* __restrict__ rinv)
{
    __shared__ float red[256];
    long base = (long)blockIdx.x * N_;
    int tid = threadIdx.x;

    float mx = -1e30f;
    for (int i = tid; i < N_; i += 256) mx = fmaxf(mx, in[base + i]);
    red[tid] = mx; __syncthreads();
    for (int s = 128; s > 0; s >>= 1) {
        if (tid < s) red[tid] = fmaxf(red[tid], red[tid + s]);
        __syncthreads();
    }
    mx = red[0]; __syncthreads();

    float sum = 0.f;
    for (int i = tid; i < N_; i += 256) sum += expf(in[base + i] - mx);
    red[tid] = sum; __syncthreads();
    for (int s = 128; s > 0; s >>= 1) {
        if (tid < s) red[tid] += red[tid + s];
        __syncthreads();
    }
    if (tid == 0) { rmx[blockIdx.x] = mx; rinv[blockIdx.x] = 1.f / red[0]; }
}

// ---------------------------------------------------------------------------
// k2_pgemm: Ppart[split][b][k][c] = sum_{pix} softmax_row(attn)[k][pix]*x[c][pix]
// row-softmax applied inline from (rmx,rinv). m = channel, n = class (all 150).
// warp layout 2(m) x 4(n); acc[4][5][4]. grid (C_/BM=4, NSPLIT, B_)
// ---------------------------------------------------------------------------
__global__ __launch_bounds__(256) void k2_pgemm(
    const float* __restrict__ Xg, const float* __restrict__ attn,
    const float* __restrict__ rmx, const float* __restrict__ rinv,
    float* __restrict__ Pp)
{
    extern __shared__ uint32_t sm[];
    uint32_t* As = sm;                         // [BM][BKp] = 4608
    uint32_t* Bs = sm + BM * BKp;              // [BN][BKp] = 5760
    float*    rs = (float*)(sm + BM * BKp + BN * BKp);  // 320 floats
    float*    Cs = (float*)sm;                 // epilogue alias

    const int tid = threadIdx.x, lane = tid & 31, warp = tid >> 5;
    const int wm = (warp & 1) * 64, wn = (warp >> 1) * 40;
    const int m0 = blockIdx.x * BM;            // channel block
    const int split = blockIdx.y, b = blockIdx.z;
    const float* Xb = Xg + (long)b * C_ * N_;
    const float* Ab = attn + (long)b * K_ * N_;

    if (tid < 160) {
        float m = 0.f, iv = 0.f;
        if (tid < K_) { m = rmx[b * K_ + tid]; iv = rinv[b * K_ + tid]; }
        rs[tid] = m; rs[160 + tid] = iv;
    }
    __syncthreads();

    float acc[4][5][4] = {};
    const int kbeg = split * CHUNK;
    for (int k0 = kbeg; k0 < kbeg + CHUNK; k0 += BK) {
        #pragma unroll
        for (int p = 0; p < 4; p++) {                  // As[m][k] from x
            int f4 = tid + p * 256;
            int r = f4 >> 3, c4 = (f4 & 7) * 4;
            const float4 f = *(const float4*)(Xb + (long)(m0 + r) * N_ + k0 + c4);
            *(uint4*)(As + r * BKp + c4) =
                make_uint4(f2tf(f.x), f2tf(f.y), f2tf(f.z), f2tf(f.w));
        }
        #pragma unroll
        for (int p = 0; p < 5; p++) {                  // Bs[n][k] = exp(attn-mx)*inv
            int f4 = tid + p * 256;
            int r = f4 >> 3, c4 = (f4 & 7) * 4;
            uint32_t v0 = 0, v1 = 0, v2 = 0, v3 = 0;
            if (r < K_) {
                const float4 f = *(const float4*)(Ab + (long)r * N_ + k0 + c4);
                float m = rs[r], iv = rs[160 + r];
                v0 = f2tf(expf(f.x - m) * iv); v1 = f2tf(expf(f.y - m) * iv);
                v2 = f2tf(expf(f.z - m) * iv); v3 = f2tf(expf(f.w - m) * iv);
            }
            *(uint4*)(Bs + r * BKp + c4) = make_uint4(v0, v1, v2, v3);
        }
        __syncthreads();
        #pragma unroll
        for (int ks = 0; ks < 4; ks++) {
            uint32_t a[4][4], bb[5][2];
            const int kc = ks * 8 + (lane & 3);
            #pragma unroll
            for (int mi = 0; mi < 4; mi++) {
                int mr = wm + mi * 16 + (lane >> 2);
                a[mi][0] = As[ mr      * BKp + kc];     a[mi][1] = As[(mr + 8) * BKp + kc];
                a[mi][2] = As[ mr      * BKp + kc + 4]; a[mi][3] = As[(mr + 8) * BKp + kc + 4];
            }
            #pragma unroll
            for (int ni = 0; ni < 5; ni++) {
                int nc = wn + ni * 8 + (lane >> 2);
                bb[ni][0] = Bs[nc * BKp + kc]; bb[ni][1] = Bs[nc * BKp + kc + 4];
            }
            #pragma unroll
            for (int mi = 0; mi < 4; mi++)
                #pragma unroll
                for (int ni = 0; ni < 5; ni++)
                    mma8(acc[mi][ni], a[mi][0], a[mi][1], a[mi][2], a[mi][3],
                         bb[ni][0], bb[ni][1]);
        }
        __syncthreads();
    }

    // stage to Cs[class][channel]
    #pragma unroll
    for (int mi = 0; mi < 4; mi++)
        #pragma unroll
        for (int ni = 0; ni < 5; ni++) {
            int mr = wm + mi * 16 + (lane >> 2);
            int nc = wn + ni * 8 + (lane & 3) * 2;
            Cs[ nc      * BMp + mr    ] = acc[mi][ni][0];
            Cs[(nc + 1) * BMp + mr    ] = acc[mi][ni][1];
            Cs[ nc      * BMp + mr + 8] = acc[mi][ni][2];
            Cs[(nc + 1) * BMp + mr + 8] = acc[mi][ni][3];
        }
    __syncthreads();

    float* Pb = Pp + ((long)split * B_ + b) * K_ * C_;
    #pragma unroll
    for (int i = 0; i < 19; i++) {
        int r = warp + i * 8;
        if (r < K_) {
            float4 v = *(float4*)(Cs + r * BMp + lane * 4);
            *(float4*)(Pb + (long)r * C_ + m0 + lane * 4) = v;
        }
    }
}

// ---------------------------------------------------------------------------
// k_masks: out = LayerNorm_k( acls·x + ST·softmax_col(attn) ), fused epilogue.
// m = pixel, n = class (all 150). warp 4(m) x 2(n); acc[2][10][4].
// grid (N_/BM, 1, B_)
// ---------------------------------------------------------------------------
__global__ __launch_bounds__(256) void k_masks(
    const float* __restrict__ x, const float* __restrict__ acls,
    const float* __restrict__ STg, const float* __restrict__ attn,
    const float* __restrict__ cmx, const float* __restrict__ cinv,
    const float* __restrict__ gamma, const float* __restrict__ beta,
    float* __restrict__ out)
{
    extern __shared__ uint32_t sm[];
    uint32_t* As = sm;                         // [BK][BMp] = 4352
    uint32_t* Bs = sm + BK * BMp;              // [BN][BKp] = 5760 (end 10112)
    float*    cm_s = (float*)(sm + BK * BMp + BN * BKp);  // 128
    float*    ci_s = cm_s + 128;                          // 128 (end 10368)
    float*    Cs   = (float*)sm;               // epilogue [BN][BMp] = 21760
    float*    mu_s = (float*)(sm + BN * BMp);  // 128
    float*    rs_s = mu_s + 128;               // 128 (total 22016 words)

    const int tid = threadIdx.x, lane = tid & 31, warp = tid >> 5;
    const int wm = (warp & 3) * 32, wn = (warp >> 2) * 80;
    const int m0 = blockIdx.x * BM;
    const int b  = blockIdx.z;

    if (tid < BM) {
        cm_s[tid] = cmx [(long)b * N_ + m0 + tid];
        ci_s[tid] = cinv[(long)b * N_ + m0 + tid];
    }
    __syncthreads();

    const float* Xb  = x    + (long)b * C_ * N_;
    const float* Ac  = acls + (long)b * K_ * C_;
    const float* Sb  = STg  + (long)b * K_ * K_;
    const float* Atb = attn + (long)b * K_ * N_;

    float acc[2][10][4] = {};

    // ---- phase 0: acls · x  (Kin = 512) ----
    for (int k0 = 0; k0 < C_; k0 += BK) {
        #pragma unroll
        for (int p = 0; p < 4; p++) {
            int r = warp + p * 8, c4 = lane * 4;
            const float4 f = *(const float4*)(Xb + (long)(k0 + r) * N_ + m0 + c4);
            *(uint4*)(As + r * BMp + c4) =
                make_uint4(f2tf(f.x), f2tf(f.y), f2tf(f.z), f2tf(f.w));
        }
        #pragma unroll
        for (int p = 0; p < 5; p++) {
            int f4 = tid + p * 256;
            int r = f4 >> 3, c4 = (f4 & 7) * 4;
            uint32_t v0 = 0, v1 = 0, v2 = 0, v3 = 0;
            if (r < K_) {
                const float4 f = *(const float4*)(Ac + (long)r * C_ + k0 + c4);
                v0 = f2tf(f.x); v1 = f2tf(f.y); v2 = f2tf(f.z); v3 = f2tf(f.w);
            }
            *(uint4*)(Bs + r * BKp + c4) = make_uint4(v0, v1, v2, v3);
        }
        __syncthreads();
        #pragma unroll
        for (int ks = 0; ks < 4; ks++) {
            uint32_t a[2][4], bb[10][2];
            const int kc = ks * 8 + (lane & 3);
            #pragma unroll
            for (int mi = 0; mi < 2; mi++) {
                int mr = wm + mi * 16 + (lane >> 2);
                a[mi][0] = As[kc * BMp + mr];       a[mi][1] = As[kc * BMp + mr + 8];
                a[mi][2] = As[(kc + 4) * BMp + mr]; a[mi][3] = As[(kc + 4) * BMp + mr + 8];
            }
            #pragma unroll
            for (int ni = 0; ni < 10; ni++) {
                int nc = wn + ni * 8 + (lane >> 2);
                bb[ni][0] = Bs[nc * BKp + kc]; bb[ni][1] = Bs[nc * BKp + kc + 4];
            }
            #pragma unroll
            for (int mi = 0; mi < 2; mi++)
                #pragma unroll
                for (int ni = 0; ni < 10; ni++)
                    mma8(acc[mi][ni], a[mi][0], a[mi][1], a[mi][2], a[mi][3],
                         bb[ni][0], bb[ni][1]);
        }
        __syncthreads();
    }

    // ---- phase 1: ST · softmax_col(attn)  (Kin = 150) ----
    for (int k0 = 0; k0 < K_; k0 += BK) {
        #pragma unroll
        for (int p = 0; p < 4; p++) {
            int r = warp + p * 8, c4 = lane * 4;
            uint32_t v0 = 0, v1 = 0, v2 = 0, v3 = 0;
            if (k0 + r < K_) {
                const float4 f = *(const float4*)(Atb + (long)(k0 + r) * N_ + m0 + c4);
                v0 = f2tf(expf(f.x - cm_s[c4    ]) * ci_s[c4    ]);
                v1 = f2tf(expf(f.y - cm_s[c4 + 1]) * ci_s[c4 + 1]);
                v2 = f2tf(expf(f.z - cm_s[c4 + 2]) * ci_s[c4 + 2]);
                v3 = f2tf(expf(f.w - cm_s[c4 + 3]) * ci_s[c4 + 3]);
            }
            *(uint4*)(As + r * BMp + c4) = make_uint4(v0, v1, v2, v3);
        }
        #pragma unroll
        for (int p = 0; p < 20; p++) {                 // ST scalar (lda=150, unaligned)
            int idx = tid + p * 256;
            int n = idx >> 5, kk = idx & 31;
            float v = 0.f;
            if (n < K_ && k0 + kk < K_) v = Sb[(long)n * K_ + k0 + kk];
            Bs[n * BKp + kk] = f2tf(v);
        }
        __syncthreads();
        #pragma unroll
        for (int ks = 0; ks < 4; ks++) {
            uint32_t a[2][4], bb[10][2];
            const int kc = ks * 8 + (lane & 3);
            #pragma unroll
            for (int mi = 0; mi < 2; mi++) {
                int mr = wm + mi * 16 + (lane >> 2);
                a[mi][0] = As[kc * BMp + mr];       a[mi][1] = As[kc * BMp + mr + 8];
                a[mi][2] = As[(kc + 4) * BMp + mr]; a[mi][3] = As[(kc + 4) * BMp + mr + 8];
            }
            #pragma unroll
            for (int ni = 0; ni < 10; ni++) {
                int nc = wn + ni * 8 + (lane >> 2);
                bb[ni][0] = Bs[nc * BKp + kc]; bb[ni][1] = Bs[nc * BKp + kc + 4];
            }
            #pragma unroll
            for (int mi = 0; mi < 2; mi++)
                #pragma unroll
                for (int ni = 0; ni < 10; ni++)
                    mma8(acc[mi][ni], a[mi][0], a[mi][1], a[mi][2], a[mi][3],
                         bb[ni][0], bb[ni][1]);
        }
        __syncthreads();
    }

    // ---- epilogue: stage, LayerNorm over k, write out ----
    #pragma unroll
    for (int mi = 0; mi < 2; mi++)
        #pragma unroll
        for (int ni = 0; ni < 10; ni++) {
            int mr = wm + mi * 16 + (lane >> 2);
            int nc = wn + ni * 8 + (lane & 3) * 2;
            Cs[ nc      * BMp + mr    ] = acc[mi][ni][0];
            Cs[(nc + 1) * BMp + mr    ] = acc[mi][ni][1];
            Cs[ nc      * BMp + mr + 8] = acc[mi][ni][2];
            Cs[(nc + 1) * BMp + mr + 8] = acc[mi][ni][3];
        }
    __syncthreads();

    if (tid < BM) {
        float s = 0.f, s2 = 0.f;
        for (int k = 0; k < K_; k++) {
            float v = Cs[k * BMp + tid];
            s += v; s2 += v * v;
        }
        float mu  = s * (1.f / K_);
        float var = s2 * (1.f / K_) - mu * mu;
        mu_s[tid] = mu;
        rs_s[tid] = rsqrtf(fmaxf(var, 0.f) + 1e-5f);
    }
    __syncthreads();

    float* Ob = out + (long)b * K_ * N_;
    #pragma unroll
    for (int i = 0; i < 19; i++) {
        int r = warp + i * 8;
        if (r < K_) {
            float g  = __ldg(&gamma[r]);
            float bt = __ldg(&beta[r]);
            int ml = lane * 4;
            float4 v = *(float4*)(Cs + r * BMp + ml);
            v.x = (v.x - mu_s[ml    ]) * rs_s[ml    ] * g + bt;
            v.y = (v.y - mu_s[ml + 1]) * rs_s[ml + 1] * g + bt;
            v.z = (v.z - mu_s[ml + 2]) * rs_s[ml + 2] * g + bt;
            v.w = (v.w - mu_s[ml + 3]) * rs_s[ml + 3] * g + bt;
            *(float4*)(Ob + (long)r * N_ + m0 + ml) = v;
        }
    }
}

// ---------------------------------------------------------------------------
// reduce split-K partials: P = sum_s Ppart[s]
// ---------------------------------------------------------------------------
__global__ void reduce_P(const float* __restrict__ Pp, float* __restrict__ P)
{
    int i = blockIdx.x * blockDim.x + threadIdx.x;
    if (i < B_ * K_ * C_) {
        float s = 0.f;
        #pragma unroll
        for (int sp = 0; sp < NSPLIT; sp++) s += Pp[(long)sp * B_ * K_ * C_ + i];
        P[i] = s;
    }
}

// ---------------------------------------------------------------------------
// SIMT NT GEMM for the small matmuls: C (+)= A * B^T
// ---------------------------------------------------------------------------
__global__ void gemm_nt(const float* __restrict__ A, int lda, long sA,
                        const float* __restrict__ Bm, int ldb, long sB,
                        float* __restrict__ Cm, int ldc, long sC,
                        int M, int N, int Kin, int accum)
{
    __shared__ float As[16][65];
    __shared__ float Bs[16][65];
    const float* Ab = A  + (long)blockIdx.z * sA;
    const float* Bb = Bm + (long)blockIdx.z * sB;
    float*       Cb = Cm + (long)blockIdx.z * sC;
    int m0 = blockIdx.y * 64, n0 = blockIdx.x * 64;
    int tid = threadIdx.x;
    int tx = tid & 15, ty = tid >> 4;
    float acc[4][4] = {};

    for (int k0 = 0; k0 < Kin; k0 += 16) {
        #pragma unroll
        for (int j = 0; j < 4; j++) {
            int i = tid + j * 256;
            int m = i >> 4, k = i & 15;
            float v = 0.f;
            if (m0 + m < M && k0 + k < Kin) v = Ab[(long)(m0 + m) * lda + k0 + k];
            As[k][m] = v;
        }
        #pragma unroll
        for (int j = 0; j < 4; j++) {
            int i = tid + j * 256;
            int n = i >> 4, k = i & 15;
            float v = 0.f;
            if (n0 + n < N && k0 + k < Kin) v = Bb[(long)(n0 + n) * ldb + k0 + k];
            Bs[k][n] = v;
        }
        __syncthreads();
        #pragma unroll
        for (int kk = 0; kk < 16; kk++) {
            float a[4], b[4];
            #pragma unroll
            for (int i = 0; i < 4; i++) a[i] = As[kk][ty + 16 * i];
            #pragma unroll
            for (int j = 0; j < 4; j++) b[j] = Bs[kk][tx + 16 * j];
            #pragma unroll
            for (int i = 0; i < 4; i++)
                #pragma unroll
                for (int j = 0; j < 4; j++)
                    acc[i][j] += a[i] * b[j];
        }
        __syncthreads();
    }

    #pragma unroll
    for (int i = 0; i < 4; i++) {
        int m = m0 + ty + 16 * i;
        if (m >= M) continue;
        #pragma unroll
        for (int j = 0; j < 4; j++) {
            int n = n0 + tx + 16 * j;
            if (n >= N) continue;
            long idx = (long)m * ldc + n;
            Cb[idx] = acc[i][j] + (accum ? Cb[idx] : 0.f);
        }
    }
}

__global__ void bcast_cls(const float* __restrict__ cls, float* __restrict__ dst)
{
    int i = blockIdx.x * blockDim.x + threadIdx.x;
    if (i < B_ * K_ * C_) dst[i] = cls[i % (K_ * C_)];
}

// ---------------------------------------------------------------------------
// kernel_launch
// ---------------------------------------------------------------------------
extern "C" void kernel_launch(void* const* d_in, const int* in_sizes, int n_in,
                              void* d_out, int out_size)
{
    const float* x      = (const float*)d_in[0];
    const float* cls    = (const float*)d_in[1];
    const float* W_cls  = (const float*)d_in[2];
    const float* W_feat = (const float*)d_in[3];
    const float* gamma  = (const float*)d_in[4];
    const float* beta   = (const float*)d_in[5];
    float* out = (float*)d_out;

    float *attn, *P, *Ppart, *acls, *M2, *ST, *cmx, *cinv, *rmx, *rinv;
    cudaGetSymbolAddress((void**)&attn,  g_attn);
    cudaGetSymbolAddress((void**)&P,     g_P);
    cudaGetSymbolAddress((void**)&Ppart, g_Ppart);
    cudaGetSymbolAddress((void**)&acls,  g_acls);
    cudaGetSymbolAddress((void**)&M2,    g_M2);
    cudaGetSymbolAddress((void**)&ST,    g_ST);
    cudaGetSymbolAddress((void**)&cmx,   g_cmx);
    cudaGetSymbolAddress((void**)&cinv,  g_cinv);
    cudaGetSymbolAddress((void**)&rmx,   g_rmx);
    cudaGetSymbolAddress((void**)&rinv,  g_rinv);

    // opt-in to >48KB dynamic smem (idempotent; legal under graph capture —
    // not a stream operation)
    cudaFuncSetAttribute(k_attn,  cudaFuncAttributeMaxDynamicSharedMemorySize,
                         SMEM_ATTN_W * 4);
    cudaFuncSetAttribute(k2_pgemm, cudaFuncAttributeMaxDynamicSharedMemorySize,
                         SMEM_K2_W * 4);
    cudaFuncSetAttribute(k_masks, cudaFuncAttributeMaxDynamicSharedMemorySize,
                         SMEM_MASK_W * 4);

    const long sP = (long)K_ * C_;
    const long sS = (long)K_ * K_;

    // M2[k][d] = sum_c cls[k][c] * W_feat[d][c]
    gemm_nt<<<dim3(8, 3, 1), 256>>>(cls, C_, 0, W_feat, C_, 0,
                                    M2, C_, 0, K_, C_, C_, 0);

    // attn + column softmax stats
    k_attn<<<dim3(N_ / BM, 1, B_), 256, SMEM_ATTN_W * 4>>>(x, cls, attn, cmx, cinv);

    // row softmax stats
    rowstats<<<B_ * K_, 256>>>(attn, rmx, rinv);

    // P = softmax_row(attn) @ img_feat   (inline exp, split-K)
    k2_pgemm<<<dim3(C_ / BM, NSPLIT, B_), 256, SMEM_K2_W * 4>>>(x, attn, rmx, rinv, Ppart);
    reduce_P<<<(B_ * K_ * C_ + 255) / 256, 256>>>(Ppart, P);

    // aligned_cls = cls + P @ W_cls^T
    bcast_cls<<<(B_ * K_ * C_ + 255) / 256, 256>>>(cls, acls);
    gemm_nt<<<dim3(8, 3, B_), 256>>>(P, C_, sP, W_cls, C_, 0,
                                     acls, C_, sP, K_, C_, C_, 1);

    // ST[b][k'][k] = sum_d acls[b][k'][d] * M2[k][d]
    gemm_nt<<<dim3(3, 3, B_), 256>>>(acls, C_, sP, M2, C_, 0,
                                     ST, K_, sS, K_, K_, C_, 0);

    // out = LN( acls·x + ST·softmax_col(attn) ), fully fused
    k_masks<<<dim3(N_ / BM, 1, B_), 256, SMEM_MASK_W * 4>>>(
        x, acls, ST, attn, cmx, cinv, gamma, beta, out);
}

// round 7
// speedup vs baseline: 6.1711x; 1.2686x over previous
#include <cuda_runtime.h>
#include <cstdint>

// Problem constants
#define B_  8
#define C_  512          // channels == D
#define N_  16384        // H*W
#define K_  150          // num classes
#define KP  160          // K padded
#define NSPLIT 8
#define CHUNK (N_ / NSPLIT)

// Tile config
#define BM  128
#define BN  160
#define BK  32
#define BMp 136   // pad: conflict-free [k][m] frag reads
#define BKp 36    // pad: conflict-free [n][k] frag reads

// stage sizes (words)
#define STG_A (32 * BMp + BN * BKp)    // k_attn / k_masks: 10112
#define STG_2 (BM * BKp + BN * BKp)    // k2: 10368
#define CS_W  (BN * BMp)               // 21760

#define SMEM_ATTN_B  (CS_W * 4)               // 87040
#define SMEM_K2_B    (CS_W * 4)               // 87040
#define CI_OFF  CS_W
#define MU_OFF  (CS_W + 128)
#define RS_OFF  (CS_W + 256)
#define SMEM_MASK_B  ((CS_W + 384) * 4)       // 88576

// ---------------------------------------------------------------------------
// Device scratch
// ---------------------------------------------------------------------------
__device__ float g_h    [B_ * KP * N_];     // h = exp(attn), rows 150..159 zero
__device__ float g_P    [B_ * K_ * C_];
__device__ float g_Ppart[NSPLIT * B_ * K_ * C_];
__device__ float g_acls [B_ * K_ * C_];
__device__ float g_M2   [K_ * C_];
__device__ float g_ST   [B_ * K_ * K_];
__device__ float g_clsT [K_ * C_];          // tf32-rounded cls
__device__ float g_aclsT[B_ * K_ * C_];     // tf32-rounded acls
__device__ float g_STT  [B_ * K_ * KP];     // tf32-rounded ST, col-padded
__device__ float g_rpart[B_ * 128 * KP];    // per-block partial row sums of h
__device__ float g_rinv [B_ * K_];
__device__ float g_cinv [B_ * N_];

// ---------------------------------------------------------------------------
// helpers
// ---------------------------------------------------------------------------
__device__ __forceinline__ uint32_t f2tf(float f) {
    uint32_t u;
    asm("cvt.rna.tf32.f32 %0, %1;" : "=r"(u) : "f"(f));
    return u;
}
__device__ __forceinline__ void mma8(float* c,
                                     uint32_t a0, uint32_t a1, uint32_t a2, uint32_t a3,
                                     uint32_t b0, uint32_t b1) {
    asm("mma.sync.aligned.m16n8k8.row.col.f32.tf32.tf32.f32 "
        "{%0,%1,%2,%3}, {%4,%5,%6,%7}, {%8,%9}, {%0,%1,%2,%3};"
        : "+f"(c[0]), "+f"(c[1]), "+f"(c[2]), "+f"(c[3])
        : "r"(a0), "r"(a1), "r"(a2), "r"(a3), "r"(b0), "r"(b1));
}
__device__ __forceinline__ void cpa16(uint32_t* smem, const float* gmem) {
    uint32_t s = (uint32_t)__cvta_generic_to_shared(smem);
    asm volatile("cp.async.cg.shared.global [%0], [%1], 16;" :: "r"(s), "l"(gmem));
}
#define CPA_COMMIT asm volatile("cp.async.commit_group;")
#define CPA_WAIT1  asm volatile("cp.async.wait_group 1;")
#define CPA_WAIT0  asm volatile("cp.async.wait_group 0;")

// ---------------------------------------------------------------------------
// k_attn: h[b][k][n] = exp( sum_c cls[k][c]*x[b][c][n] ), plus per-block row
// partial sums and per-pixel col sums. m=pixel(128), n=class(160).
// warps 4(m) x 2(n); acc[2][10][4]. grid (N_/BM, 1, B_)
// ---------------------------------------------------------------------------
__global__ __launch_bounds__(256) void k_attn(
    const float* __restrict__ x, const float* __restrict__ clsT,
    float* __restrict__ h, float* __restrict__ rpart, float* __restrict__ cinv)
{
    extern __shared__ uint32_t sm[];
    float* Cs = (float*)sm;

    const int tid = threadIdx.x, lane = tid & 31, warp = tid >> 5;
    const int wm = (warp & 3) * 32, wn = (warp >> 2) * 80;
    const int m0 = blockIdx.x * BM;
    const int b  = blockIdx.z;
    const float* Xb = x + (long)b * C_ * N_;

    // zero Bs rows 150..159 in both stages (never written by cp.async)
    for (int i = tid; i < 2 * 10 * BKp; i += 256) {
        int s = i / (10 * BKp), rem = i % (10 * BKp);
        sm[s * STG_A + 32 * BMp + (150 + rem / BKp) * BKp + rem % BKp] = 0;
    }

    auto issue = [&](int kt, int st) {
        uint32_t* As = sm + st * STG_A;
        uint32_t* Bs = As + 32 * BMp;
        const int k0 = kt * BK;
        #pragma unroll
        for (int p = 0; p < 4; p++) {                   // As[k][m] <- x raw
            int slot = tid + p * 256;
            int r = slot >> 5, c = slot & 31;
            cpa16(As + r * BMp + c * 4, Xb + (long)(k0 + r) * N_ + m0 + c * 4);
        }
        #pragma unroll
        for (int p = 0; p < 5; p++) {                   // Bs[n][k] <- clsT
            int slot = tid + p * 256;
            if (slot < K_ * 8) {
                int r = slot >> 3, c = slot & 7;
                cpa16(Bs + r * BKp + c * 4, clsT + (long)r * C_ + k0 + c * 4);
            }
        }
        CPA_COMMIT;
    };

    issue(0, 0);
    float acc[2][10][4] = {};
    const int KT = C_ / BK;                             // 16
    for (int kt = 0; kt < KT; kt++) {
        const int cur = kt & 1;
        if (kt + 1 < KT) { issue(kt + 1, cur ^ 1); CPA_WAIT1; } else { CPA_WAIT0; }
        __syncthreads();
        uint32_t* As = sm + cur * STG_A;
        uint32_t* Bs = As + 32 * BMp;
        #pragma unroll
        for (int ks = 0; ks < 4; ks++) {
            uint32_t a[2][4], bb[10][2];
            const int kc = ks * 8 + (lane & 3);
            #pragma unroll
            for (int mi = 0; mi < 2; mi++) {
                int mr = wm + mi * 16 + (lane >> 2);
                a[mi][0] = As[kc * BMp + mr];       a[mi][1] = As[kc * BMp + mr + 8];
                a[mi][2] = As[(kc + 4) * BMp + mr]; a[mi][3] = As[(kc + 4) * BMp + mr + 8];
            }
            #pragma unroll
            for (int ni = 0; ni < 10; ni++) {
                int nc = wn + ni * 8 + (lane >> 2);
                bb[ni][0] = Bs[nc * BKp + kc]; bb[ni][1] = Bs[nc * BKp + kc + 4];
            }
            #pragma unroll
            for (int mi = 0; mi < 2; mi++)
                #pragma unroll
                for (int ni = 0; ni < 10; ni++)
                    mma8(acc[mi][ni], a[mi][0], a[mi][1], a[mi][2], a[mi][3],
                         bb[ni][0], bb[ni][1]);
        }
        __syncthreads();
    }

    // stage h = exp(acc) into Cs[class][pixel]
    #pragma unroll
    for (int mi = 0; mi < 2; mi++)
        #pragma unroll
        for (int ni = 0; ni < 10; ni++) {
            int mr = wm + mi * 16 + (lane >> 2);
            int nc = wn + ni * 8 + (lane & 3) * 2;
            Cs[ nc      * BMp + mr    ] = expf(acc[mi][ni][0]);
            Cs[(nc + 1) * BMp + mr    ] = expf(acc[mi][ni][1]);
            Cs[ nc      * BMp + mr + 8] = expf(acc[mi][ni][2]);
            Cs[(nc + 1) * BMp + mr + 8] = expf(acc[mi][ni][3]);
        }
    __syncthreads();

    float* Hb = h + (long)b * KP * N_;
    #pragma unroll
    for (int i = 0; i < 19; i++) {
        int r = warp + i * 8;
        if (r < K_) {
            float4 v = *(float4*)(Cs + r * BMp + lane * 4);
            *(float4*)(Hb + (long)r * N_ + m0 + lane * 4) = v;
            float s = v.x + v.y + v.z + v.w;
            #pragma unroll
            for (int o = 16; o > 0; o >>= 1) s += __shfl_xor_sync(0xffffffffu, s, o);
            if (lane == 0) rpart[((long)b * 128 + blockIdx.x) * KP + r] = s;
        }
    }
    if (tid < BM) {
        float s = 0.f;
        for (int k = 0; k < K_; k++) s += Cs[k * BMp + tid];
        cinv[(long)b * N_ + m0 + tid] = 1.f / s;
    }
}

// ---------------------------------------------------------------------------
// k2_pgemm: Ppart[split][b][k][c] = sum_{pix in chunk} h[k][pix] * x[c][pix]
// (row-softmax normalizer applied later in reduce_P). m=channel, n=class.
// warps 2(m) x 4(n); acc[4][5][4]. grid (C_/BM=4, NSPLIT, B_)
// ---------------------------------------------------------------------------
__global__ __launch_bounds__(256) void k2_pgemm(
    const float* __restrict__ Xg, const float* __restrict__ h,
    float* __restrict__ Pp)
{
    extern __shared__ uint32_t sm[];
    float* Cs = (float*)sm;

    const int tid = threadIdx.x, lane = tid & 31, warp = tid >> 5;
    const int wm = (warp & 1) * 64, wn = (warp >> 1) * 40;
    const int m0 = blockIdx.x * BM;
    const int split = blockIdx.y, b = blockIdx.z;
    const float* Xb = Xg + (long)b * C_ * N_;
    const float* Hb = h  + (long)b * KP * N_;

    for (int i = tid; i < 2 * 10 * BKp; i += 256) {
        int s = i / (10 * BKp), rem = i % (10 * BKp);
        sm[s * STG_2 + BM * BKp + (150 + rem / BKp) * BKp + rem % BKp] = 0;
    }

    const int kbeg = split * CHUNK;
    auto issue = [&](int kt, int st) {
        uint32_t* As = sm + st * STG_2;
        uint32_t* Bs = As + BM * BKp;
        const int k0 = kbeg + kt * BK;
        #pragma unroll
        for (int p = 0; p < 4; p++) {                   // As[m][k] <- x raw
            int slot = tid + p * 256;
            int r = slot >> 3, c = slot & 7;
            cpa16(As + r * BKp + c * 4, Xb + (long)(m0 + r) * N_ + k0 + c * 4);
        }
        #pragma unroll
        for (int p = 0; p < 5; p++) {                   // Bs[n][k] <- h raw
            int slot = tid + p * 256;
            if (slot < K_ * 8) {
                int r = slot >> 3, c = slot & 7;
                cpa16(Bs + r * BKp + c * 4, Hb + (long)r * N_ + k0 + c * 4);
            }
        }
        CPA_COMMIT;
    };

    issue(0, 0);
    float acc[4][5][4] = {};
    const int KT = CHUNK / BK;                          // 64
    for (int kt = 0; kt < KT; kt++) {
        const int cur = kt & 1;
        if (kt + 1 < KT) { issue(kt + 1, cur ^ 1); CPA_WAIT1; } else { CPA_WAIT0; }
        __syncthreads();
        uint32_t* As = sm + cur * STG_2;
        uint32_t* Bs = As + BM * BKp;
        #pragma unroll
        for (int ks = 0; ks < 4; ks++) {
            uint32_t a[4][4], bb[5][2];
            const int kc = ks * 8 + (lane & 3);
            #pragma unroll
            for (int mi = 0; mi < 4; mi++) {
                int mr = wm + mi * 16 + (lane >> 2);
                a[mi][0] = As[ mr      * BKp + kc];     a[mi][1] = As[(mr + 8) * BKp + kc];
                a[mi][2] = As[ mr      * BKp + kc + 4]; a[mi][3] = As[(mr + 8) * BKp + kc + 4];
            }
            #pragma unroll
            for (int ni = 0; ni < 5; ni++) {
                int nc = wn + ni * 8 + (lane >> 2);
                bb[ni][0] = Bs[nc * BKp + kc]; bb[ni][1] = Bs[nc * BKp + kc + 4];
            }
            #pragma unroll
            for (int mi = 0; mi < 4; mi++)
                #pragma unroll
                for (int ni = 0; ni < 5; ni++)
                    mma8(acc[mi][ni], a[mi][0], a[mi][1], a[mi][2], a[mi][3],
                         bb[ni][0], bb[ni][1]);
        }
        __syncthreads();
    }

    #pragma unroll
    for (int mi = 0; mi < 4; mi++)
        #pragma unroll
        for (int ni = 0; ni < 5; ni++) {
            int mr = wm + mi * 16 + (lane >> 2);
            int nc = wn + ni * 8 + (lane & 3) * 2;
            Cs[ nc      * BMp + mr    ] = acc[mi][ni][0];
            Cs[(nc + 1) * BMp + mr    ] = acc[mi][ni][1];
            Cs[ nc      * BMp + mr + 8] = acc[mi][ni][2];
            Cs[(nc + 1) * BMp + mr + 8] = acc[mi][ni][3];
        }
    __syncthreads();

    float* Pb = Pp + ((long)split * B_ + b) * K_ * C_;
    #pragma unroll
    for (int i = 0; i < 19; i++) {
        int r = warp + i * 8;
        if (r < K_) {
            float4 v = *(float4*)(Cs + r * BMp + lane * 4);
            *(float4*)(Pb + (long)r * C_ + m0 + lane * 4) = v;
        }
    }
}

// ---------------------------------------------------------------------------
// k_masks: out = LN_k( acls·x + ST·(h·cinv) ). Unified 21-tile pipeline:
// tiles 0..15 phase0 (x vs aclsT), 16..20 phase1 (h vs STT, cinv applied at
// fragment load). grid (N_/BM, 1, B_)
// ---------------------------------------------------------------------------
__global__ __launch_bounds__(256) void k_masks(
    const float* __restrict__ x, const float* __restrict__ aclsT,
    const float* __restrict__ STT, const float* __restrict__ h,
    const float* __restrict__ cinv,
    const float* __restrict__ gamma, const float* __restrict__ beta,
    float* __restrict__ out)
{
    extern __shared__ uint32_t sm[];
    float* Cs   = (float*)sm;
    float* ci_s = (float*)(sm + CI_OFF);
    float* mu_s = (float*)(sm + MU_OFF);
    float* rs_s = (float*)(sm + RS_OFF);

    const int tid = threadIdx.x, lane = tid & 31, warp = tid >> 5;
    const int wm = (warp & 3) * 32, wn = (warp >> 2) * 80;
    const int m0 = blockIdx.x * BM;
    const int b  = blockIdx.z;

    const float* Xb = x     + (long)b * C_ * N_;
    const float* Ab = aclsT + (long)b * K_ * C_;
    const float* Sb = STT   + (long)b * K_ * KP;
    const float* Hb = h     + (long)b * KP * N_;

    if (tid < BM) ci_s[tid] = cinv[(long)b * N_ + m0 + tid];
    for (int i = tid; i < 2 * 10 * BKp; i += 256) {
        int s = i / (10 * BKp), rem = i % (10 * BKp);
        sm[s * STG_A + 32 * BMp + (150 + rem / BKp) * BKp + rem % BKp] = 0;
    }

    auto issue = [&](int kt, int st) {
        uint32_t* As = sm + st * STG_A;
        uint32_t* Bs = As + 32 * BMp;
        if (kt < 16) {
            const int k0 = kt * BK;
            #pragma unroll
            for (int p = 0; p < 4; p++) {
                int slot = tid + p * 256;
                int r = slot >> 5, c = slot & 31;
                cpa16(As + r * BMp + c * 4, Xb + (long)(k0 + r) * N_ + m0 + c * 4);
            }
            #pragma unroll
            for (int p = 0; p < 5; p++) {
                int slot = tid + p * 256;
                if (slot < K_ * 8) {
                    int r = slot >> 3, c = slot & 7;
                    cpa16(Bs + r * BKp + c * 4, Ab + (long)r * C_ + k0 + c * 4);
                }
            }
        } else {
            const int k0 = (kt - 16) * BK;
            #pragma unroll
            for (int p = 0; p < 4; p++) {               // As[k][m] <- h (padded rows)
                int slot = tid + p * 256;
                int r = slot >> 5, c = slot & 31;
                cpa16(As + r * BMp + c * 4, Hb + (long)(k0 + r) * N_ + m0 + c * 4);
            }
            #pragma unroll
            for (int p = 0; p < 5; p++) {               // Bs[n][k] <- STT (padded cols)
                int slot = tid + p * 256;
                if (slot < K_ * 8) {
                    int r = slot >> 3, c = slot & 7;
                    cpa16(Bs + r * BKp + c * 4, Sb + (long)r * KP + k0 + c * 4);
                }
            }
        }
        CPA_COMMIT;
    };

    issue(0, 0);
    float acc[2][10][4] = {};
    const int KT = 16 + 5;
    for (int kt = 0; kt < KT; kt++) {
        const int cur = kt & 1;
        if (kt + 1 < KT) { issue(kt + 1, cur ^ 1); CPA_WAIT1; } else { CPA_WAIT0; }
        __syncthreads();
        uint32_t* As = sm + cur * STG_A;
        uint32_t* Bs = As + 32 * BMp;
        const bool ph1 = (kt >= 16);
        #pragma unroll
        for (int ks = 0; ks < 4; ks++) {
            uint32_t a[2][4], bb[10][2];
            const int kc = ks * 8 + (lane & 3);
            #pragma unroll
            for (int mi = 0; mi < 2; mi++) {
                int mr = wm + mi * 16 + (lane >> 2);
                if (!ph1) {
                    a[mi][0] = As[kc * BMp + mr];       a[mi][1] = As[kc * BMp + mr + 8];
                    a[mi][2] = As[(kc + 4) * BMp + mr]; a[mi][3] = As[(kc + 4) * BMp + mr + 8];
                } else {
                    float c0 = ci_s[mr], c1 = ci_s[mr + 8];
                    a[mi][0] = f2tf(__uint_as_float(As[kc * BMp + mr])       * c0);
                    a[mi][1] = f2tf(__uint_as_float(As[kc * BMp + mr + 8])   * c1);
                    a[mi][2] = f2tf(__uint_as_float(As[(kc + 4) * BMp + mr])     * c0);
                    a[mi][3] = f2tf(__uint_as_float(As[(kc + 4) * BMp + mr + 8]) * c1);
                }
            }
            #pragma unroll
            for (int ni = 0; ni < 10; ni++) {
                int nc = wn + ni * 8 + (lane >> 2);
                bb[ni][0] = Bs[nc * BKp + kc]; bb[ni][1] = Bs[nc * BKp + kc + 4];
            }
            #pragma unroll
            for (int mi = 0; mi < 2; mi++)
                #pragma unroll
                for (int ni = 0; ni < 10; ni++)
                    mma8(acc[mi][ni], a[mi][0], a[mi][1], a[mi][2], a[mi][3],
                         bb[ni][0], bb[ni][1]);
        }
        __syncthreads();
    }

    // stage, LayerNorm over k, write out
    #pragma unroll
    for (int mi = 0; mi < 2; mi++)
        #pragma unroll
        for (int ni = 0; ni < 10; ni++) {
            int mr = wm + mi * 16 + (lane >> 2);
            int nc = wn + ni * 8 + (lane & 3) * 2;
            Cs[ nc      * BMp + mr    ] = acc[mi][ni][0];
            Cs[(nc + 1) * BMp + mr    ] = acc[mi][ni][1];
            Cs[ nc      * BMp + mr + 8] = acc[mi][ni][2];
            Cs[(nc + 1) * BMp + mr + 8] = acc[mi][ni][3];
        }
    __syncthreads();

    if (tid < BM) {
        float s = 0.f, s2 = 0.f;
        for (int k = 0; k < K_; k++) {
            float v = Cs[k * BMp + tid];
            s += v; s2 += v * v;
        }
        float mu  = s * (1.f / K_);
        float var = s2 * (1.f / K_) - mu * mu;
        mu_s[tid] = mu;
        rs_s[tid] = rsqrtf(fmaxf(var, 0.f) + 1e-5f);
    }
    __syncthreads();

    float* Ob = out + (long)b * K_ * N_;
    #pragma unroll
    for (int i = 0; i < 19; i++) {
        int r = warp + i * 8;
        if (r < K_) {
            float g  = __ldg(&gamma[r]);
            float bt = __ldg(&beta[r]);
            int ml = lane * 4;
            float4 v = *(float4*)(Cs + r * BMp + ml);
            v.x = (v.x - mu_s[ml    ]) * rs_s[ml    ] * g + bt;
            v.y = (v.y - mu_s[ml + 1]) * rs_s[ml + 1] * g + bt;
            v.z = (v.z - mu_s[ml + 2]) * rs_s[ml + 2] * g + bt;
            v.w = (v.w - mu_s[ml + 3]) * rs_s[ml + 3] * g + bt;
            *(float4*)(Ob + (long)r * N_ + m0 + ml) = v;
        }
    }
}

// ---------------------------------------------------------------------------
// small kernels
// ---------------------------------------------------------------------------
__global__ void reduce_rinv(const float* __restrict__ rpart, float* __restrict__ rinv)
{
    int idx = blockIdx.x * blockDim.x + threadIdx.x;
    if (idx < B_ * K_) {
        int b = idx / K_, k = idx % K_;
        float s = 0.f;
        for (int blk = 0; blk < 128; blk++)
            s += rpart[((long)b * 128 + blk) * KP + k];
        rinv[idx] = 1.f / s;
    }
}

__global__ void reduce_P(const float* __restrict__ Pp, const float* __restrict__ rinv,
                         float* __restrict__ P)
{
    int i = blockIdx.x * blockDim.x + threadIdx.x;
    if (i < B_ * K_ * C_) {
        int b = i / (K_ * C_);
        int k = (i / C_) % K_;
        float s = 0.f;
        #pragma unroll
        for (int sp = 0; sp < NSPLIT; sp++) s += Pp[(long)sp * B_ * K_ * C_ + i];
        P[i] = s * rinv[b * K_ + k];
    }
}

__global__ void conv_tf32(const float* __restrict__ in, float* __restrict__ out, int n)
{
    int i = blockIdx.x * blockDim.x + threadIdx.x;
    if (i < n) out[i] = __uint_as_float(f2tf(in[i]));
}

__global__ void conv_ST(const float* __restrict__ ST, float* __restrict__ STT)
{
    int i = blockIdx.x * blockDim.x + threadIdx.x;
    if (i < B_ * K_ * KP) {
        int c  = i % KP;
        int rk = i / KP;           // b*K_ + row
        float v = 0.f;
        if (c < K_) v = __uint_as_float(f2tf(ST[(long)rk * K_ + c]));
        STT[i] = v;
    }
}

__global__ void zero_hpad(float* __restrict__ h)
{
    int i = blockIdx.x * blockDim.x + threadIdx.x;
    int tot = B_ * (KP - K_) * N_;
    if (i < tot) {
        int b = i / ((KP - K_) * N_);
        int rem = i % ((KP - K_) * N_);
        h[(long)b * KP * N_ + (long)K_ * N_ + rem] = 0.f;
    }
}

__global__ void bcast_cls(const float* __restrict__ cls, float* __restrict__ dst)
{
    int i = blockIdx.x * blockDim.x + threadIdx.x;
    if (i < B_ * K_ * C_) dst[i] = cls[i % (K_ * C_)];
}

// SIMT NT GEMM for the small matmuls: C (+)= A * B^T
__global__ void gemm_nt(const float* __restrict__ A, int lda, long sA,
                        const float* __restrict__ Bm, int ldb, long sB,
                        float* __restrict__ Cm, int ldc, long sC,
                        int M, int N, int Kin, int accum)
{
    __shared__ float As[16][65];
    __shared__ float Bs[16][65];
    const float* Abp = A  + (long)blockIdx.z * sA;
    const float* Bbp = Bm + (long)blockIdx.z * sB;
    float*       Cbp = Cm + (long)blockIdx.z * sC;
    int m0 = blockIdx.y * 64, n0 = blockIdx.x * 64;
    int tid = threadIdx.x;
    int tx = tid & 15, ty = tid >> 4;
    float acc[4][4] = {};

    for (int k0 = 0; k0 < Kin; k0 += 16) {
        #pragma unroll
        for (int j = 0; j < 4; j++) {
            int i = tid + j * 256;
            int m = i >> 4, k = i & 15;
            float v = 0.f;
            if (m0 + m < M && k0 + k < Kin) v = Abp[(long)(m0 + m) * lda + k0 + k];
            As[k][m] = v;
        }
        #pragma unroll
        for (int j = 0; j < 4; j++) {
            int i = tid + j * 256;
            int n = i >> 4, k = i & 15;
            float v = 0.f;
            if (n0 + n < N && k0 + k < Kin) v = Bbp[(long)(n0 + n) * ldb + k0 + k];
            Bs[k][n] = v;
        }
        __syncthreads();
        #pragma unroll
        for (int kk = 0; kk < 16; kk++) {
            float a[4], bv[4];
            #pragma unroll
            for (int i = 0; i < 4; i++) a[i] = As[kk][ty + 16 * i];
            #pragma unroll
            for (int j = 0; j < 4; j++) bv[j] = Bs[kk][tx + 16 * j];
            #pragma unroll
            for (int i = 0; i < 4; i++)
                #pragma unroll
                for (int j = 0; j < 4; j++)
                    acc[i][j] += a[i] * bv[j];
        }
        __syncthreads();
    }

    #pragma unroll
    for (int i = 0; i < 4; i++) {
        int m = m0 + ty + 16 * i;
        if (m >= M) continue;
        #pragma unroll
        for (int j = 0; j < 4; j++) {
            int n = n0 + tx + 16 * j;
            if (n >= N) continue;
            long idx = (long)m * ldc + n;
            Cbp[idx] = acc[i][j] + (accum ? Cbp[idx] : 0.f);
        }
    }
}

// ---------------------------------------------------------------------------
// kernel_launch
// ---------------------------------------------------------------------------
extern "C" void kernel_launch(void* const* d_in, const int* in_sizes, int n_in,
                              void* d_out, int out_size)
{
    const float* x      = (const float*)d_in[0];
    const float* cls    = (const float*)d_in[1];
    const float* W_cls  = (const float*)d_in[2];
    const float* W_feat = (const float*)d_in[3];
    const float* gamma  = (const float*)d_in[4];
    const float* beta   = (const float*)d_in[5];
    float* out = (float*)d_out;

    float *h, *P, *Ppart, *acls, *M2, *ST, *clsT, *aclsT, *STT, *rpart, *rinv, *cinv;
    cudaGetSymbolAddress((void**)&h,     g_h);
    cudaGetSymbolAddress((void**)&P,     g_P);
    cudaGetSymbolAddress((void**)&Ppart, g_Ppart);
    cudaGetSymbolAddress((void**)&acls,  g_acls);
    cudaGetSymbolAddress((void**)&M2,    g_M2);
    cudaGetSymbolAddress((void**)&ST,    g_ST);
    cudaGetSymbolAddress((void**)&clsT,  g_clsT);
    cudaGetSymbolAddress((void**)&aclsT, g_aclsT);
    cudaGetSymbolAddress((void**)&STT,   g_STT);
    cudaGetSymbolAddress((void**)&rpart, g_rpart);
    cudaGetSymbolAddress((void**)&rinv,  g_rinv);
    cudaGetSymbolAddress((void**)&cinv,  g_cinv);

    cudaFuncSetAttribute(k_attn,  cudaFuncAttributeMaxDynamicSharedMemorySize, SMEM_ATTN_B);
    cudaFuncSetAttribute(k2_pgemm, cudaFuncAttributeMaxDynamicSharedMemorySize, SMEM_K2_B);
    cudaFuncSetAttribute(k_masks, cudaFuncAttributeMaxDynamicSharedMemorySize, SMEM_MASK_B);

    const long sP = (long)K_ * C_;
    const long sS = (long)K_ * K_;

    // prep: tf32 cls, zero h padding, M2
    conv_tf32<<<(K_ * C_ + 255) / 256, 256>>>(cls, clsT, K_ * C_);
    zero_hpad<<<(B_ * (KP - K_) * N_ + 255) / 256, 256>>>(h);
    gemm_nt<<<dim3(8, 3, 1), 256>>>(cls, C_, 0, W_feat, C_, 0,
                                    M2, C_, 0, K_, C_, C_, 0);

    // h = exp(attn) + row partials + col inverses
    k_attn<<<dim3(N_ / BM, 1, B_), 256, SMEM_ATTN_B>>>(x, clsT, h, rpart, cinv);
    reduce_rinv<<<(B_ * K_ + 255) / 256, 256>>>(rpart, rinv);

    // P = rowsoftmax @ img_feat  (unnormalized in k2, scaled in reduce)
    k2_pgemm<<<dim3(C_ / BM, NSPLIT, B_), 256, SMEM_K2_B>>>(x, h, Ppart);
    reduce_P<<<(B_ * K_ * C_ + 255) / 256, 256>>>(Ppart, rinv, P);

    // aligned_cls = cls + P @ W_cls^T ; tf32 copy
    bcast_cls<<<(B_ * K_ * C_ + 255) / 256, 256>>>(cls, acls);
    gemm_nt<<<dim3(8, 3, B_), 256>>>(P, C_, sP, W_cls, C_, 0,
                                     acls, C_, sP, K_, C_, C_, 1);
    conv_tf32<<<(B_ * K_ * C_ + 255) / 256, 256>>>(acls, aclsT, B_ * K_ * C_);

    // ST = acls @ M2^T ; tf32 padded copy
    gemm_nt<<<dim3(3, 3, B_), 256>>>(acls, C_, sP, M2, C_, 0,
                                     ST, K_, sS, K_, K_, C_, 0);
    conv_ST<<<(B_ * K_ * KP + 255) / 256, 256>>>(ST, STT);

    // out = LN( acls·x + ST·(h·cinv) )
    k_masks<<<dim3(N_ / BM, 1, B_), 256, SMEM_MASK_B>>>(
        x, aclsT, STT, h, cinv, gamma, beta, out);
}

// round 10
// speedup vs baseline: 6.7145x; 1.0881x over previous
#include <cuda_runtime.h>
#include <cstdint>

// Problem constants
#define B_  8
#define C_  512          // channels == D
#define N_  16384        // H*W
#define K_  150          // num classes
#define KP  160          // K padded
#define NSPLIT 8
#define CHUNK (N_ / NSPLIT)

// Tile config
#define BM  128
#define BN  160
#define BK  32
#define BMp 136   // pad: conflict-free [k][m] frag reads
#define BKp 36    // pad: conflict-free [n][k] frag reads

// stage sizes (words)
#define STG_A (32 * BMp + BN * BKp)    // k_attn / k_masks: 10112
#define STG_2 (BM * BKp + BN * BKp)    // k2: 10368
#define CS_W  (BN * BMp)               // 21760

#define SMEM_ATTN_B  (CS_W * 4)               // 87040
#define SMEM_K2_B    (CS_W * 4)               // 87040
#define CI_OFF  CS_W
#define MU_OFF  (CS_W + 128)
#define RS_OFF  (CS_W + 256)
#define SMEM_MASK_B  ((CS_W + 384) * 4)       // 88576

// ---------------------------------------------------------------------------
// Device scratch
// ---------------------------------------------------------------------------
__device__ float g_h    [B_ * KP * N_];     // h = exp(attn), rows 150..159 zero
__device__ float g_P    [B_ * K_ * C_];
__device__ float g_Ppart[NSPLIT * B_ * K_ * C_];
__device__ float g_M2   [K_ * C_];
__device__ float g_clsT [K_ * C_];          // tf32-rounded cls
__device__ float g_aclsT[B_ * K_ * C_];     // tf32-rounded aligned_cls
__device__ float g_STT  [B_ * K_ * KP];     // tf32-rounded ST, col-padded
__device__ float g_rpart[B_ * 128 * KP];    // per-block partial row sums of h
__device__ float g_rinv [B_ * K_];
__device__ float g_cinv [B_ * N_];

// ---------------------------------------------------------------------------
// helpers
// ---------------------------------------------------------------------------
__device__ __forceinline__ uint32_t f2tf(float f) {
    uint32_t u;
    asm("cvt.rna.tf32.f32 %0, %1;" : "=r"(u) : "f"(f));
    return u;
}
__device__ __forceinline__ void mma8(float* c,
                                     uint32_t a0, uint32_t a1, uint32_t a2, uint32_t a3,
                                     uint32_t b0, uint32_t b1) {
    asm("mma.sync.aligned.m16n8k8.row.col.f32.tf32.tf32.f32 "
        "{%0,%1,%2,%3}, {%4,%5,%6,%7}, {%8,%9}, {%0,%1,%2,%3};"
        : "+f"(c[0]), "+f"(c[1]), "+f"(c[2]), "+f"(c[3])
        : "r"(a0), "r"(a1), "r"(a2), "r"(a3), "r"(b0), "r"(b1));
}
__device__ __forceinline__ void cpa16(uint32_t* smem, const float* gmem) {
    uint32_t s = (uint32_t)__cvta_generic_to_shared(smem);
    asm volatile("cp.async.cg.shared.global [%0], [%1], 16;" :: "r"(s), "l"(gmem));
}
#define CPA_COMMIT asm volatile("cp.async.commit_group;")
#define CPA_WAIT0  asm volatile("cp.async.wait_group 0;")

// ---------------------------------------------------------------------------
// k_attn: h[b][k][n] = exp( sum_c cls[k][c]*x[b][c][n] ), plus per-block row
// partial sums and per-pixel col-sum inverses. m=pixel(128), n=class(160).
// warps 4(m) x 2(n); acc[2][10][4]. grid (N_/BM, 1, B_). Single-sync pipeline.
// ---------------------------------------------------------------------------
__global__ __launch_bounds__(256, 2) void k_attn(
    const float* __restrict__ x, const float* __restrict__ clsT,
    float* __restrict__ h, float* __restrict__ rpart, float* __restrict__ cinv)
{
    extern __shared__ uint32_t sm[];
    float* Cs = (float*)sm;

    const int tid = threadIdx.x, lane = tid & 31, warp = tid >> 5;
    const int wm = (warp & 3) * 32, wn = (warp >> 2) * 80;
    const int m0 = blockIdx.x * BM;
    const int b  = blockIdx.z;
    const float* Xb = x + (long)b * C_ * N_;

    // zero Bs rows 150..159 in both stages (never written by cp.async)
    for (int i = tid; i < 2 * 10 * BKp; i += 256) {
        int s = i / (10 * BKp), rem = i % (10 * BKp);
        sm[s * STG_A + 32 * BMp + (150 + rem / BKp) * BKp + rem % BKp] = 0;
    }

    auto issue = [&](int kt, int st) {
        uint32_t* As = sm + st * STG_A;
        uint32_t* Bs = As + 32 * BMp;
        const int k0 = kt * BK;
        #pragma unroll
        for (int p = 0; p < 4; p++) {                   // As[k][m] <- x raw
            int slot = tid + p * 256;
            int r = slot >> 5, c = slot & 31;
            cpa16(As + r * BMp + c * 4, Xb + (long)(k0 + r) * N_ + m0 + c * 4);
        }
        #pragma unroll
        for (int p = 0; p < 5; p++) {                   // Bs[n][k] <- clsT
            int slot = tid + p * 256;
            if (slot < K_ * 8) {
                int r = slot >> 3, c = slot & 7;
                cpa16(Bs + r * BKp + c * 4, clsT + (long)r * C_ + k0 + c * 4);
            }
        }
        CPA_COMMIT;
    };

    issue(0, 0);
    float acc[2][10][4] = {};
    const int KT = C_ / BK;                             // 16
    for (int kt = 0; kt < KT; kt++) {
        const int cur = kt & 1;
        CPA_WAIT0;
        __syncthreads();
        if (kt + 1 < KT) issue(kt + 1, cur ^ 1);
        uint32_t* As = sm + cur * STG_A;
        uint32_t* Bs = As + 32 * BMp;
        #pragma unroll
        for (int ks = 0; ks < 4; ks++) {
            uint32_t a[2][4], bb[10][2];
            const int kc = ks * 8 + (lane & 3);
            #pragma unroll
            for (int mi = 0; mi < 2; mi++) {
                int mr = wm + mi * 16 + (lane >> 2);
                a[mi][0] = As[kc * BMp + mr];       a[mi][1] = As[kc * BMp + mr + 8];
                a[mi][2] = As[(kc + 4) * BMp + mr]; a[mi][3] = As[(kc + 4) * BMp + mr + 8];
            }
            #pragma unroll
            for (int ni = 0; ni < 10; ni++) {
                int nc = wn + ni * 8 + (lane >> 2);
                bb[ni][0] = Bs[nc * BKp + kc]; bb[ni][1] = Bs[nc * BKp + kc + 4];
            }
            #pragma unroll
            for (int mi = 0; mi < 2; mi++)
                #pragma unroll
                for (int ni = 0; ni < 10; ni++)
                    mma8(acc[mi][ni], a[mi][0], a[mi][1], a[mi][2], a[mi][3],
                         bb[ni][0], bb[ni][1]);
        }
    }
    __syncthreads();

    // stage h = exp(acc) into Cs[class][pixel]
    #pragma unroll
    for (int mi = 0; mi < 2; mi++)
        #pragma unroll
        for (int ni = 0; ni < 10; ni++) {
            int mr = wm + mi * 16 + (lane >> 2);
            int nc = wn + ni * 8 + (lane & 3) * 2;
            Cs[ nc      * BMp + mr    ] = expf(acc[mi][ni][0]);
            Cs[(nc + 1) * BMp + mr    ] = expf(acc[mi][ni][1]);
            Cs[ nc      * BMp + mr + 8] = expf(acc[mi][ni][2]);
            Cs[(nc + 1) * BMp + mr + 8] = expf(acc[mi][ni][3]);
        }
    __syncthreads();

    float* Hb = h + (long)b * KP * N_;
    #pragma unroll
    for (int i = 0; i < 19; i++) {
        int r = warp + i * 8;
        if (r < K_) {
            float4 v = *(float4*)(Cs + r * BMp + lane * 4);
            *(float4*)(Hb + (long)r * N_ + m0 + lane * 4) = v;
            float s = v.x + v.y + v.z + v.w;
            #pragma unroll
            for (int o = 16; o > 0; o >>= 1) s += __shfl_xor_sync(0xffffffffu, s, o);
            if (lane == 0) rpart[((long)b * 128 + blockIdx.x) * KP + r] = s;
        }
    }
    if (tid < BM) {
        float s = 0.f;
        for (int k = 0; k < K_; k++) s += Cs[k * BMp + tid];
        cinv[(long)b * N_ + m0 + tid] = 1.f / s;
    }
}

// ---------------------------------------------------------------------------
// k2_pgemm: Ppart[split][b][k][c] = sum_{pix in chunk} h[k][pix] * x[c][pix]
// m=channel, n=class. warps 2(m) x 4(n); acc[4][5][4].
// grid (C_/BM=4, NSPLIT, B_). Single-sync pipeline.
// ---------------------------------------------------------------------------
__global__ __launch_bounds__(256, 2) void k2_pgemm(
    const float* __restrict__ Xg, const float* __restrict__ h,
    float* __restrict__ Pp)
{
    extern __shared__ uint32_t sm[];
    float* Cs = (float*)sm;

    const int tid = threadIdx.x, lane = tid & 31, warp = tid >> 5;
    const int wm = (warp & 1) * 64, wn = (warp >> 1) * 40;
    const int m0 = blockIdx.x * BM;
    const int split = blockIdx.y, b = blockIdx.z;
    const float* Xb = Xg + (long)b * C_ * N_;
    const float* Hb = h  + (long)b * KP * N_;

    for (int i = tid; i < 2 * 10 * BKp; i += 256) {
        int s = i / (10 * BKp), rem = i % (10 * BKp);
        sm[s * STG_2 + BM * BKp + (150 + rem / BKp) * BKp + rem % BKp] = 0;
    }

    const int kbeg = split * CHUNK;
    auto issue = [&](int kt, int st) {
        uint32_t* As = sm + st * STG_2;
        uint32_t* Bs = As + BM * BKp;
        const int k0 = kbeg + kt * BK;
        #pragma unroll
        for (int p = 0; p < 4; p++) {                   // As[m][k] <- x raw
            int slot = tid + p * 256;
            int r = slot >> 3, c = slot & 7;
            cpa16(As + r * BKp + c * 4, Xb + (long)(m0 + r) * N_ + k0 + c * 4);
        }
        #pragma unroll
        for (int p = 0; p < 5; p++) {                   // Bs[n][k] <- h raw
            int slot = tid + p * 256;
            if (slot < K_ * 8) {
                int r = slot >> 3, c = slot & 7;
                cpa16(Bs + r * BKp + c * 4, Hb + (long)r * N_ + k0 + c * 4);
            }
        }
        CPA_COMMIT;
    };

    issue(0, 0);
    float acc[4][5][4] = {};
    const int KT = CHUNK / BK;                          // 64
    for (int kt = 0; kt < KT; kt++) {
        const int cur = kt & 1;
        CPA_WAIT0;
        __syncthreads();
        if (kt + 1 < KT) issue(kt + 1, cur ^ 1);
        uint32_t* As = sm + cur * STG_2;
        uint32_t* Bs = As + BM * BKp;
        #pragma unroll
        for (int ks = 0; ks < 4; ks++) {
            uint32_t a[4][4], bb[5][2];
            const int kc = ks * 8 + (lane & 3);
            #pragma unroll
            for (int mi = 0; mi < 4; mi++) {
                int mr = wm + mi * 16 + (lane >> 2);
                a[mi][0] = As[ mr      * BKp + kc];     a[mi][1] = As[(mr + 8) * BKp + kc];
                a[mi][2] = As[ mr      * BKp + kc + 4]; a[mi][3] = As[(mr + 8) * BKp + kc + 4];
            }
            #pragma unroll
            for (int ni = 0; ni < 5; ni++) {
                int nc = wn + ni * 8 + (lane >> 2);
                bb[ni][0] = Bs[nc * BKp + kc]; bb[ni][1] = Bs[nc * BKp + kc + 4];
            }
            #pragma unroll
            for (int mi = 0; mi < 4; mi++)
                #pragma unroll
                for (int ni = 0; ni < 5; ni++)
                    mma8(acc[mi][ni], a[mi][0], a[mi][1], a[mi][2], a[mi][3],
                         bb[ni][0], bb[ni][1]);
        }
    }
    __syncthreads();

    #pragma unroll
    for (int mi = 0; mi < 4; mi++)
        #pragma unroll
        for (int ni = 0; ni < 5; ni++) {
            int mr = wm + mi * 16 + (lane >> 2);
            int nc = wn + ni * 8 + (lane & 3) * 2;
            Cs[ nc      * BMp + mr    ] = acc[mi][ni][0];
            Cs[(nc + 1) * BMp + mr    ] = acc[mi][ni][1];
            Cs[ nc      * BMp + mr + 8] = acc[mi][ni][2];
            Cs[(nc + 1) * BMp + mr + 8] = acc[mi][ni][3];
        }
    __syncthreads();

    float* Pb = Pp + ((long)split * B_ + b) * K_ * C_;
    #pragma unroll
    for (int i = 0; i < 19; i++) {
        int r = warp + i * 8;
        if (r < K_) {
            float4 v = *(float4*)(Cs + r * BMp + lane * 4);
            *(float4*)(Pb + (long)r * C_ + m0 + lane * 4) = v;
        }
    }
}

// ---------------------------------------------------------------------------
// k_masks: out = LN_k( acls·x + ST·(h·cinv) ). Unified 21-tile single-sync
// pipeline: tiles 0..15 phase0 (x vs aclsT), 16..20 phase1 (h vs STT, cinv
// applied at fragment load). grid (N_/BM, 1, B_)
// ---------------------------------------------------------------------------
__global__ __launch_bounds__(256, 2) void k_masks(
    const float* __restrict__ x, const float* __restrict__ aclsT,
    const float* __restrict__ STT, const float* __restrict__ h,
    const float* __restrict__ cinv,
    const float* __restrict__ gamma, const float* __restrict__ beta,
    float* __restrict__ out)
{
    extern __shared__ uint32_t sm[];
    float* Cs   = (float*)sm;
    float* ci_s = (float*)(sm + CI_OFF);
    float* mu_s = (float*)(sm + MU_OFF);
    float* rs_s = (float*)(sm + RS_OFF);

    const int tid = threadIdx.x, lane = tid & 31, warp = tid >> 5;
    const int wm = (warp & 3) * 32, wn = (warp >> 2) * 80;
    const int m0 = blockIdx.x * BM;
    const int b  = blockIdx.z;

    const float* Xb = x     + (long)b * C_ * N_;
    const float* Ab = aclsT + (long)b * K_ * C_;
    const float* Sb = STT   + (long)b * K_ * KP;
    const float* Hb = h     + (long)b * KP * N_;

    if (tid < BM) ci_s[tid] = cinv[(long)b * N_ + m0 + tid];
    for (int i = tid; i < 2 * 10 * BKp; i += 256) {
        int s = i / (10 * BKp), rem = i % (10 * BKp);
        sm[s * STG_A + 32 * BMp + (150 + rem / BKp) * BKp + rem % BKp] = 0;
    }

    auto issue = [&](int kt, int st) {
        uint32_t* As = sm + st * STG_A;
        uint32_t* Bs = As + 32 * BMp;
        if (kt < 16) {
            const int k0 = kt * BK;
            #pragma unroll
            for (int p = 0; p < 4; p++) {
                int slot = tid + p * 256;
                int r = slot >> 5, c = slot & 31;
                cpa16(As + r * BMp + c * 4, Xb + (long)(k0 + r) * N_ + m0 + c * 4);
            }
            #pragma unroll
            for (int p = 0; p < 5; p++) {
                int slot = tid + p * 256;
                if (slot < K_ * 8) {
                    int r = slot >> 3, c = slot & 7;
                    cpa16(Bs + r * BKp + c * 4, Ab + (long)r * C_ + k0 + c * 4);
                }
            }
        } else {
            const int k0 = (kt - 16) * BK;
            #pragma unroll
            for (int p = 0; p < 4; p++) {               // As[k][m] <- h (padded rows)
                int slot = tid + p * 256;
                int r = slot >> 5, c = slot & 31;
                cpa16(As + r * BMp + c * 4, Hb + (long)(k0 + r) * N_ + m0 + c * 4);
            }
            #pragma unroll
            for (int p = 0; p < 5; p++) {               // Bs[n][k] <- STT (padded cols)
                int slot = tid + p * 256;
                if (slot < K_ * 8) {
                    int r = slot >> 3, c = slot & 7;
                    cpa16(Bs + r * BKp + c * 4, Sb + (long)r * KP + k0 + c * 4);
                }
            }
        }
        CPA_COMMIT;
    };

    issue(0, 0);
    float acc[2][10][4] = {};
    const int KT = 16 + 5;
    for (int kt = 0; kt < KT; kt++) {
        const int cur = kt & 1;
        CPA_WAIT0;
        __syncthreads();
        if (kt + 1 < KT) issue(kt + 1, cur ^ 1);
        uint32_t* As = sm + cur * STG_A;
        uint32_t* Bs = As + 32 * BMp;
        const bool ph1 = (kt >= 16);
        #pragma unroll
        for (int ks = 0; ks < 4; ks++) {
            uint32_t a[2][4], bb[10][2];
            const int kc = ks * 8 + (lane & 3);
            #pragma unroll
            for (int mi = 0; mi < 2; mi++) {
                int mr = wm + mi * 16 + (lane >> 2);
                if (!ph1) {
                    a[mi][0] = As[kc * BMp + mr];       a[mi][1] = As[kc * BMp + mr + 8];
                    a[mi][2] = As[(kc + 4) * BMp + mr]; a[mi][3] = As[(kc + 4) * BMp + mr + 8];
                } else {
                    float c0 = ci_s[mr], c1 = ci_s[mr + 8];
                    a[mi][0] = f2tf(__uint_as_float(As[kc * BMp + mr])       * c0);
                    a[mi][1] = f2tf(__uint_as_float(As[kc * BMp + mr + 8])   * c1);
                    a[mi][2] = f2tf(__uint_as_float(As[(kc + 4) * BMp + mr])     * c0);
                    a[mi][3] = f2tf(__uint_as_float(As[(kc + 4) * BMp + mr + 8]) * c1);
                }
            }
            #pragma unroll
            for (int ni = 0; ni < 10; ni++) {
                int nc = wn + ni * 8 + (lane >> 2);
                bb[ni][0] = Bs[nc * BKp + kc]; bb[ni][1] = Bs[nc * BKp + kc + 4];
            }
            #pragma unroll
            for (int mi = 0; mi < 2; mi++)
                #pragma unroll
                for (int ni = 0; ni < 10; ni++)
                    mma8(acc[mi][ni], a[mi][0], a[mi][1], a[mi][2], a[mi][3],
                         bb[ni][0], bb[ni][1]);
        }
    }
    __syncthreads();

    // stage, LayerNorm over k, write out
    #pragma unroll
    for (int mi = 0; mi < 2; mi++)
        #pragma unroll
        for (int ni = 0; ni < 10; ni++) {
            int mr = wm + mi * 16 + (lane >> 2);
            int nc = wn + ni * 8 + (lane & 3) * 2;
            Cs[ nc      * BMp + mr    ] = acc[mi][ni][0];
            Cs[(nc + 1) * BMp + mr    ] = acc[mi][ni][1];
            Cs[ nc      * BMp + mr + 8] = acc[mi][ni][2];
            Cs[(nc + 1) * BMp + mr + 8] = acc[mi][ni][3];
        }
    __syncthreads();

    if (tid < BM) {
        float s = 0.f, s2 = 0.f;
        for (int k = 0; k < K_; k++) {
            float v = Cs[k * BMp + tid];
            s += v; s2 += v * v;
        }
        float mu  = s * (1.f / K_);
        float var = s2 * (1.f / K_) - mu * mu;
        mu_s[tid] = mu;
        rs_s[tid] = rsqrtf(fmaxf(var, 0.f) + 1e-5f);
    }
    __syncthreads();

    float* Ob = out + (long)b * K_ * N_;
    #pragma unroll
    for (int i = 0; i < 19; i++) {
        int r = warp + i * 8;
        if (r < K_) {
            float g  = __ldg(&gamma[r]);
            float bt = __ldg(&beta[r]);
            int ml = lane * 4;
            float4 v = *(float4*)(Cs + r * BMp + ml);
            v.x = (v.x - mu_s[ml    ]) * rs_s[ml    ] * g + bt;
            v.y = (v.y - mu_s[ml + 1]) * rs_s[ml + 1] * g + bt;
            v.z = (v.z - mu_s[ml + 2]) * rs_s[ml + 2] * g + bt;
            v.w = (v.w - mu_s[ml + 3]) * rs_s[ml + 3] * g + bt;
            *(float4*)(Ob + (long)r * N_ + m0 + ml) = v;
        }
    }
}

// ---------------------------------------------------------------------------
// small kernels
// ---------------------------------------------------------------------------
__global__ void reduce_rinv(const float* __restrict__ rpart, float* __restrict__ rinv)
{
    int idx = blockIdx.x * blockDim.x + threadIdx.x;
    if (idx < B_ * K_) {
        int b = idx / K_, k = idx % K_;
        float s = 0.f;
        for (int blk = 0; blk < 128; blk++)
            s += rpart[((long)b * 128 + blk) * KP + k];
        rinv[idx] = 1.f / s;
    }
}

__global__ void reduce_P(const float* __restrict__ Pp, const float* __restrict__ rinv,
                         float* __restrict__ P)
{
    int i = blockIdx.x * blockDim.x + threadIdx.x;
    if (i < B_ * K_ * C_) {
        int b = i / (K_ * C_);
        int k = (i / C_) % K_;
        float s = 0.f;
        #pragma unroll
        for (int sp = 0; sp < NSPLIT; sp++) s += Pp[(long)sp * B_ * K_ * C_ + i];
        P[i] = s * rinv[b * K_ + k];
    }
}

__global__ void conv_tf32(const float* __restrict__ in, float* __restrict__ out, int n)
{
    int i = blockIdx.x * blockDim.x + threadIdx.x;
    if (i < n) out[i] = __uint_as_float(f2tf(in[i]));
}

__global__ void zero_hpad(float* __restrict__ h)
{
    int i = blockIdx.x * blockDim.x + threadIdx.x;
    int tot = B_ * (KP - K_) * N_;
    if (i < tot) {
        int b = i / ((KP - K_) * N_);
        int rem = i % ((KP - K_) * N_);
        h[(long)b * KP * N_ + (long)K_ * N_ + rem] = 0.f;
    }
}

// plain SIMT NT GEMM (used for M2 = cls @ W_feat^T)
__global__ void gemm_nt(const float* __restrict__ A, int lda,
                        const float* __restrict__ Bm, int ldb,
                        float* __restrict__ Cm, int ldc,
                        int M, int N, int Kin)
{
    __shared__ float As[16][65];
    __shared__ float Bs[16][65];
    int m0 = blockIdx.y * 64, n0 = blockIdx.x * 64;
    int tid = threadIdx.x;
    int tx = tid & 15, ty = tid >> 4;
    float acc[4][4] = {};

    for (int k0 = 0; k0 < Kin; k0 += 16) {
        #pragma unroll
        for (int j = 0; j < 4; j++) {
            int i = tid + j * 256;
            int m = i >> 4, k = i & 15;
            float v = 0.f;
            if (m0 + m < M && k0 + k < Kin) v = A[(long)(m0 + m) * lda + k0 + k];
            As[k][m] = v;
        }
        #pragma unroll
        for (int j = 0; j < 4; j++) {
            int i = tid + j * 256;
            int n = i >> 4, k = i & 15;
            float v = 0.f;
            if (n0 + n < N && k0 + k < Kin) v = Bm[(long)(n0 + n) * ldb + k0 + k];
            Bs[k][n] = v;
        }
        __syncthreads();
        #pragma unroll
        for (int kk = 0; kk < 16; kk++) {
            float a[4], bv[4];
            #pragma unroll
            for (int i = 0; i < 4; i++) a[i] = As[kk][ty + 16 * i];
            #pragma unroll
            for (int j = 0; j < 4; j++) bv[j] = Bs[kk][tx + 16 * j];
            #pragma unroll
            for (int i = 0; i < 4; i++)
                #pragma unroll
                for (int j = 0; j < 4; j++)
                    acc[i][j] += a[i] * bv[j];
        }
        __syncthreads();
    }

    #pragma unroll
    for (int i = 0; i < 4; i++) {
        int m = m0 + ty + 16 * i;
        if (m >= M) continue;
        #pragma unroll
        for (int j = 0; j < 4; j++) {
            int n = n0 + tx + 16 * j;
            if (n >= N) continue;
            Cm[(long)m * ldc + n] = acc[i][j];
        }
    }
}

// gemm_acls: aclsT[b] = tf32( cls + P[b] @ W_cls^T ). grid (8, 3, B_)
__global__ void gemm_acls(const float* __restrict__ P, const float* __restrict__ Wc,
                          const float* __restrict__ cls, float* __restrict__ aclsT)
{
    __shared__ float As[16][65];
    __shared__ float Bs[16][65];
    const float* Ab = P + (long)blockIdx.z * K_ * C_;
    float*       Cb = aclsT + (long)blockIdx.z * K_ * C_;
    int m0 = blockIdx.y * 64, n0 = blockIdx.x * 64;
    int tid = threadIdx.x;
    int tx = tid & 15, ty = tid >> 4;
    float acc[4][4] = {};

    for (int k0 = 0; k0 < C_; k0 += 16) {
        #pragma unroll
        for (int j = 0; j < 4; j++) {
            int i = tid + j * 256;
            int m = i >> 4, k = i & 15;
            float v = 0.f;
            if (m0 + m < K_) v = Ab[(long)(m0 + m) * C_ + k0 + k];
            As[k][m] = v;
        }
        #pragma unroll
        for (int j = 0; j < 4; j++) {
            int i = tid + j * 256;
            int n = i >> 4, k = i & 15;
            Bs[k][n] = Wc[(long)(n0 + n) * C_ + k0 + k];
        }
        __syncthreads();
        #pragma unroll
        for (int kk = 0; kk < 16; kk++) {
            float a[4], bv[4];
            #pragma unroll
            for (int i = 0; i < 4; i++) a[i] = As[kk][ty + 16 * i];
            #pragma unroll
            for (int j = 0; j < 4; j++) bv[j] = Bs[kk][tx + 16 * j];
            #pragma unroll
            for (int i = 0; i < 4; i++)
                #pragma unroll
                for (int j = 0; j < 4; j++)
                    acc[i][j] += a[i] * bv[j];
        }
        __syncthreads();
    }

    #pragma unroll
    for (int i = 0; i < 4; i++) {
        int m = m0 + ty + 16 * i;
        if (m >= K_) continue;
        #pragma unroll
        for (int j = 0; j < 4; j++) {
            int n = n0 + tx + 16 * j;
            float v = acc[i][j] + cls[(long)m * C_ + n];
            Cb[(long)m * C_ + n] = __uint_as_float(f2tf(v));
        }
    }
}

// gemm_STT: STT[b][k'][k] = tf32( sum_d aclsT[b][k'][d] * M2[k][d] ), k padded
// to KP with zeros. grid (3, 3, B_)  (covers 192x192 >= 150x160)
__global__ void gemm_STT(const float* __restrict__ aclsT, const float* __restrict__ M2,
                         float* __restrict__ STT)
{
    __shared__ float As[16][65];
    __shared__ float Bs[16][65];
    const float* Ab = aclsT + (long)blockIdx.z * K_ * C_;
    float*       Cb = STT   + (long)blockIdx.z * K_ * KP;
    int m0 = blockIdx.y * 64, n0 = blockIdx.x * 64;
    int tid = threadIdx.x;
    int tx = tid & 15, ty = tid >> 4;
    float acc[4][4] = {};

    for (int k0 = 0; k0 < C_; k0 += 16) {
        #pragma unroll
        for (int j = 0; j < 4; j++) {
            int i = tid + j * 256;
            int m = i >> 4, k = i & 15;
            float v = 0.f;
            if (m0 + m < K_) v = Ab[(long)(m0 + m) * C_ + k0 + k];
            As[k][m] = v;
        }
        #pragma unroll
        for (int j = 0; j < 4; j++) {
            int i = tid + j * 256;
            int n = i >> 4, k = i & 15;
            float v = 0.f;
            if (n0 + n < K_) v = M2[(long)(n0 + n) * C_ + k0 + k];
            Bs[k][n] = v;
        }
        __syncthreads();
        #pragma unroll
        for (int kk = 0; kk < 16; kk++) {
            float a[4], bv[4];
            #pragma unroll
            for (int i = 0; i < 4; i++) a[i] = As[kk][ty + 16 * i];
            #pragma unroll
            for (int j = 0; j < 4; j++) bv[j] = Bs[kk][tx + 16 * j];
            #pragma unroll
            for (int i = 0; i < 4; i++)
                #pragma unroll
                for (int j = 0; j < 4; j++)
                    acc[i][j] += a[i] * bv[j];
        }
        __syncthreads();
    }

    #pragma unroll
    for (int i = 0; i < 4; i++) {
        int m = m0 + ty + 16 * i;
        if (m >= K_) continue;
        #pragma unroll
        for (int j = 0; j < 4; j++) {
            int n = n0 + tx + 16 * j;
            if (n >= KP) continue;
            float v = (n < K_) ? __uint_as_float(f2tf(acc[i][j])) : 0.f;
            Cb[(long)m * KP + n] = v;
        }
    }
}

// ---------------------------------------------------------------------------
// kernel_launch
// ---------------------------------------------------------------------------
extern "C" void kernel_launch(void* const* d_in, const int* in_sizes, int n_in,
                              void* d_out, int out_size)
{
    const float* x      = (const float*)d_in[0];
    const float* cls    = (const float*)d_in[1];
    const float* W_cls  = (const float*)d_in[2];
    const float* W_feat = (const float*)d_in[3];
    const float* gamma  = (const float*)d_in[4];
    const float* beta   = (const float*)d_in[5];
    float* out = (float*)d_out;

    float *h, *P, *Ppart, *M2, *clsT, *aclsT, *STT, *rpart, *rinv, *cinv;
    cudaGetSymbolAddress((void**)&h,     g_h);
    cudaGetSymbolAddress((void**)&P,     g_P);
    cudaGetSymbolAddress((void**)&Ppart, g_Ppart);
    cudaGetSymbolAddress((void**)&M2,    g_M2);
    cudaGetSymbolAddress((void**)&clsT,  g_clsT);
    cudaGetSymbolAddress((void**)&aclsT, g_aclsT);
    cudaGetSymbolAddress((void**)&STT,   g_STT);
    cudaGetSymbolAddress((void**)&rpart, g_rpart);
    cudaGetSymbolAddress((void**)&rinv,  g_rinv);
    cudaGetSymbolAddress((void**)&cinv,  g_cinv);

    cudaFuncSetAttribute(k_attn,  cudaFuncAttributeMaxDynamicSharedMemorySize, SMEM_ATTN_B);
    cudaFuncSetAttribute(k2_pgemm, cudaFuncAttributeMaxDynamicSharedMemorySize, SMEM_K2_B);
    cudaFuncSetAttribute(k_masks, cudaFuncAttributeMaxDynamicSharedMemorySize, SMEM_MASK_B);

    // prep: tf32 cls, zero h padding, M2 = cls @ W_feat^T
    conv_tf32<<<(K_ * C_ + 255) / 256, 256>>>(cls, clsT, K_ * C_);
    zero_hpad<<<(B_ * (KP - K_) * N_ + 255) / 256, 256>>>(h);
    gemm_nt<<<dim3(8, 3, 1), 256>>>(cls, C_, W_feat, C_, M2, C_, K_, C_, C_);

    // h = exp(attn) + row partials + col inverses
    k_attn<<<dim3(N_ / BM, 1, B_), 256, SMEM_ATTN_B>>>(x, clsT, h, rpart, cinv);
    reduce_rinv<<<(B_ * K_ + 255) / 256, 256>>>(rpart, rinv);

    // P = rowsoftmax @ img_feat  (unnormalized in k2, scaled in reduce)
    k2_pgemm<<<dim3(C_ / BM, NSPLIT, B_), 256, SMEM_K2_B>>>(x, h, Ppart);
    reduce_P<<<(B_ * K_ * C_ + 255) / 256, 256>>>(Ppart, rinv, P);

    // aclsT = tf32(cls + P @ W_cls^T); STT = tf32(aclsT @ M2^T) padded
    gemm_acls<<<dim3(8, 3, B_), 256>>>(P, W_cls, cls, aclsT);
    gemm_STT<<<dim3(3, 3, B_), 256>>>(aclsT, M2, STT);

    // out = LN( acls·x + ST·(h·cinv) )
    k_masks<<<dim3(N_ / BM, 1, B_), 256, SMEM_MASK_B>>>(
        x, aclsT, STT, h, cinv, gamma, beta, out);
}